// round 1
// baseline (speedup 1.0000x reference)
#include <cuda_runtime.h>
#include <cuda_bf16.h>
#include <stdint.h>

// ---------------------------------------------------------------------------
// Problem constants
// ---------------------------------------------------------------------------
#define N_KERNELS 10000
#define IN_CH 3
#define BATCH 64
#define T_LEN 1024
#define MAXK 11
#define W_STRIDE (IN_CH * MAXK)   // 33 floats per kernel
#define PADL 80                   // max pad = ((11-1)/2)*16 = 80
#define XPITCH (T_LEN + 2 * PADL) // 1184
#define NGROUPS 15
#define CHUNK 8
#define MAXCHUNKS 1266            // <= 10000/8 + 15
#define OUT_STRIDE (2 * N_KERNELS)

// ---------------------------------------------------------------------------
// Device-global scratch (no allocations allowed)
// ---------------------------------------------------------------------------
__device__ uint8_t g_didx[N_KERNELS];   // dilation index 0..4 from RNG
__device__ uint8_t g_kidx_rng[N_KERNELS];
__device__ uint8_t g_garr[N_KERNELS];   // group id 0..14
__device__ int     g_sorted[N_KERNELS]; // kernel ids sorted by group
__device__ int     g_nchunks;
__device__ int4    g_chunks[MAXCHUNKS]; // {start, count, k, d}
__device__ float   g_wT[MAXCHUNKS * 33 * CHUNK]; // [chunk][tap][8]
__device__ float   g_biasT[MAXCHUNKS * CHUNK];

__constant__ int c_dils[5] = {1, 2, 4, 8, 16};

// ---------------------------------------------------------------------------
// NumPy default_rng(0) reproduction: SeedSequence -> PCG64 (XSL-RR) -> Lemire
// ---------------------------------------------------------------------------
struct Pcg {
    unsigned long long shi, slo;  // 128-bit state
    unsigned long long ihi, ilo;  // 128-bit inc
    int has32;
    unsigned int buf;
};

__device__ __forceinline__ void pcg_step(Pcg &p) {
    const unsigned long long MH = 2549297995355413924ull;
    const unsigned long long ML = 4865540595714422341ull;
    unsigned long long nlo = p.slo * ML;
    unsigned long long nhi = __umul64hi(p.slo, ML) + p.shi * ML + p.slo * MH;
    unsigned long long alo = nlo + p.ilo;
    unsigned long long ahi = nhi + p.ihi + (alo < nlo ? 1ull : 0ull);
    p.slo = alo; p.shi = ahi;
}

__device__ __forceinline__ unsigned long long pcg_next64(Pcg &p) {
    pcg_step(p);
    unsigned int rot = (unsigned int)(p.shi >> 58);
    unsigned long long x = p.shi ^ p.slo;
    return (x >> rot) | (x << ((64u - rot) & 63u));
}

__device__ __forceinline__ unsigned int pcg_next32(Pcg &p) {
    if (p.has32) { p.has32 = 0; return p.buf; }
    unsigned long long v = pcg_next64(p);
    p.has32 = 1;
    p.buf = (unsigned int)(v >> 32);
    return (unsigned int)v;
}

// Lemire bounded sample over [0, excl) with NumPy's exact rejection logic
__device__ __forceinline__ unsigned int lemire32(Pcg &p, unsigned int excl) {
    unsigned long long m = (unsigned long long)pcg_next32(p) * (unsigned long long)excl;
    unsigned int leftover = (unsigned int)m;
    if (leftover < excl) {
        unsigned int thr = (unsigned int)(0u - excl) % excl;
        while (leftover < thr) {
            m = (unsigned long long)pcg_next32(p) * (unsigned long long)excl;
            leftover = (unsigned int)m;
        }
    }
    return (unsigned int)(m >> 32);
}

__device__ __forceinline__ unsigned int hashmix32(unsigned int v, unsigned int *hc) {
    v ^= *hc;
    *hc *= 0x931e8875u;
    v *= *hc;
    v ^= v >> 16;
    return v;
}

__device__ __forceinline__ unsigned int mix32(unsigned int x, unsigned int y) {
    unsigned int r = x * 0xca01f9ddu - y * 0x4973f715u;
    r ^= r >> 16;
    return r;
}

__global__ void rng_kernel() {
    if (threadIdx.x != 0 || blockIdx.x != 0) return;

    // SeedSequence(0): entropy = [0], pool_size = 4
    unsigned int pool[4];
    unsigned int hc = 0x43b0d7e5u;  // INIT_A
    for (int i = 0; i < 4; i++) pool[i] = hashmix32(0u, &hc);
    for (int s = 0; s < 4; s++)
        for (int d = 0; d < 4; d++)
            if (s != d) pool[d] = mix32(pool[d], hashmix32(pool[s], &hc));

    // generate_state(4, uint64) -> 8 uint32 words (little-endian pairs)
    unsigned int hb = 0x8b51f9ddu;  // INIT_B
    unsigned int w32[8];
    for (int i = 0; i < 8; i++) {
        unsigned int v = pool[i & 3];
        v ^= hb;
        hb *= 0x58f38dedu;  // MULT_B
        v *= hb;
        v ^= v >> 16;
        w32[i] = v;
    }
    unsigned long long s0 = (unsigned long long)w32[0] | ((unsigned long long)w32[1] << 32); // initstate hi
    unsigned long long s1 = (unsigned long long)w32[2] | ((unsigned long long)w32[3] << 32); // initstate lo
    unsigned long long s2 = (unsigned long long)w32[4] | ((unsigned long long)w32[5] << 32); // initseq hi
    unsigned long long s3 = (unsigned long long)w32[6] | ((unsigned long long)w32[7] << 32); // initseq lo

    Pcg p;
    p.shi = 0; p.slo = 0;
    p.ihi = (s2 << 1) | (s3 >> 63);
    p.ilo = (s3 << 1) | 1ull;
    p.has32 = 0; p.buf = 0;
    pcg_step(p);
    unsigned long long alo = p.slo + s1;
    p.shi = p.shi + s0 + (alo < p.slo ? 1ull : 0ull);
    p.slo = alo;
    pcg_step(p);

    // First integers(0,3,10000) call, then integers(0,5,10000)
    for (int i = 0; i < N_KERNELS; i++) g_kidx_rng[i] = (uint8_t)lemire32(p, 3u);
    for (int i = 0; i < N_KERNELS; i++) g_didx[i]     = (uint8_t)lemire32(p, 5u);
}

// ---------------------------------------------------------------------------
// Group kernels by (k, d); counting sort; build chunk table
// ---------------------------------------------------------------------------
__global__ void group_kernel(const float* __restrict__ weights) {
    __shared__ int cnt[NGROUPS];
    __shared__ int off[NGROUPS + 1];
    __shared__ int scnt[NGROUPS];

    int tid = threadIdx.x;
    if (tid < NGROUPS) cnt[tid] = 0;
    __syncthreads();

    for (int i = tid; i < N_KERNELS; i += blockDim.x) {
        const float* w = weights + i * W_STRIDE;
        bool t11 = false, t9 = false;
        #pragma unroll
        for (int c = 0; c < 3; c++) {
            t11 |= (w[c * MAXK + 9] != 0.0f) | (w[c * MAXK + 10] != 0.0f);
            t9  |= (w[c * MAXK + 7] != 0.0f) | (w[c * MAXK + 8]  != 0.0f);
        }
        int kidx = t11 ? 2 : (t9 ? 1 : 0);  // weight-mask-derived (robust)
        int g = kidx * 5 + (int)g_didx[i];
        g_garr[i] = (uint8_t)g;
        atomicAdd(&cnt[g], 1);
    }
    __syncthreads();

    if (tid == 0) {
        off[0] = 0;
        for (int g = 0; g < NGROUPS; g++) off[g + 1] = off[g] + cnt[g];
        int nch = 0;
        for (int g = 0; g < NGROUPS; g++) {
            int ks = 7 + 2 * (g / 5);
            int d  = c_dils[g % 5];
            int n  = cnt[g];
            int base = off[g];
            for (int s = 0; s < n; s += CHUNK) {
                int4 ch;
                ch.x = base + s;
                ch.y = (n - s < CHUNK) ? (n - s) : CHUNK;
                ch.z = ks;
                ch.w = d;
                g_chunks[nch++] = ch;
            }
        }
        g_nchunks = nch;
        for (int g = 0; g < NGROUPS; g++) scnt[g] = off[g];
    }
    __syncthreads();

    for (int i = tid; i < N_KERNELS; i += blockDim.x) {
        int g = g_garr[i];
        int p = atomicAdd(&scnt[g], 1);
        g_sorted[p] = i;
    }
}

// ---------------------------------------------------------------------------
// Transpose weights into [chunk][tap(c*k+j)][8] layout + biases
// ---------------------------------------------------------------------------
__global__ void wt_kernel(const float* __restrict__ weights,
                          const float* __restrict__ biases) {
    int ci = blockIdx.x;
    if (ci >= g_nchunks) return;
    int4 ch = g_chunks[ci];
    int start = ch.x, count = ch.y, k = ch.z;
    int ntap = 3 * k;

    for (int idx = threadIdx.x; idx < 33 * CHUNK; idx += blockDim.x) {
        int q = idx & 7;
        int tap = idx >> 3;
        float v = 0.0f;
        if (q < count && tap < ntap) {
            int i = g_sorted[start + q];
            int c = tap / k;
            int j = tap - c * k;
            v = weights[i * W_STRIDE + c * MAXK + j];
        }
        g_wT[ci * (33 * CHUNK) + idx] = v;
    }
    if (threadIdx.x < CHUNK) {
        float b = 0.0f;
        if (threadIdx.x < count) b = biases[g_sorted[start + threadIdx.x]];
        g_biasT[ci * CHUNK + threadIdx.x] = b;
    }
}

// ---------------------------------------------------------------------------
// Main conv + max/ppv kernel
// ---------------------------------------------------------------------------
template <int K>
__device__ __forceinline__ void conv_loop(const float* __restrict__ sx,
                                          const float* __restrict__ sw,
                                          int d, int t0, float acc[8][8]) {
    const int h = (K - 1) / 2;
    #pragma unroll
    for (int c = 0; c < 3; c++) {
        const float* xb = sx + c * XPITCH + PADL - h * d + t0;
        #pragma unroll
        for (int j = 0; j < K; j++) {
            const float4* wp = (const float4*)(sw + (c * K + j) * CHUNK);
            float4 wa = wp[0];
            float4 wb = wp[1];
            const float* xp = xb + j * d;
            float xv[8];
            #pragma unroll
            for (int r = 0; r < 8; r++) xv[r] = xp[r * 32];
            #pragma unroll
            for (int r = 0; r < 8; r++) {
                acc[r][0] = fmaf(xv[r], wa.x, acc[r][0]);
                acc[r][1] = fmaf(xv[r], wa.y, acc[r][1]);
                acc[r][2] = fmaf(xv[r], wa.z, acc[r][2]);
                acc[r][3] = fmaf(xv[r], wa.w, acc[r][3]);
                acc[r][4] = fmaf(xv[r], wb.x, acc[r][4]);
                acc[r][5] = fmaf(xv[r], wb.y, acc[r][5]);
                acc[r][6] = fmaf(xv[r], wb.z, acc[r][6]);
                acc[r][7] = fmaf(xv[r], wb.w, acc[r][7]);
            }
        }
    }
}

__global__ void __launch_bounds__(128, 4)
rocket_main(const float* __restrict__ x, float* __restrict__ out) {
    __shared__ __align__(16) float sx[3 * XPITCH];
    __shared__ __align__(16) float sw[33 * CHUNK];
    __shared__ float sb[CHUNK];
    __shared__ float sred[4][CHUNK][2];

    const int nch = g_nchunks;
    const long long nit = (long long)nch * BATCH;
    const int nb = gridDim.x;
    long long s = (long long)blockIdx.x * nit / nb;
    long long e = (long long)(blockIdx.x + 1) * nit / nb;
    if (s >= e) return;

    int b  = (int)(s / nch);
    int ci = (int)(s - (long long)b * nch);
    int curb = -1;

    const int warp = threadIdx.x >> 5;
    const int lane = threadIdx.x & 31;
    const int t0 = warp * 256 + lane;

    for (long long it = s; it < e; it++) {
        if (b != curb) {
            __syncthreads();
            for (int idx = threadIdx.x; idx < 3 * XPITCH; idx += 128) sx[idx] = 0.0f;
            __syncthreads();
            for (int idx = threadIdx.x; idx < 3 * T_LEN; idx += 128) {
                int c = idx >> 10;
                int t = idx & (T_LEN - 1);
                sx[c * XPITCH + PADL + t] = x[b * 3 * T_LEN + idx];
            }
            curb = b;
        }
        __syncthreads();  // previous iteration fully done with sw/sred

        int4 ch = g_chunks[ci];
        for (int idx = threadIdx.x; idx < 33 * CHUNK; idx += 128)
            sw[idx] = g_wT[ci * (33 * CHUNK) + idx];
        if (threadIdx.x < CHUNK) sb[threadIdx.x] = g_biasT[ci * CHUNK + threadIdx.x];
        __syncthreads();

        float acc[8][8];
        #pragma unroll
        for (int r = 0; r < 8; r++)
            #pragma unroll
            for (int q = 0; q < 8; q++) acc[r][q] = sb[q];

        int d = ch.w;
        if (ch.z == 7)       conv_loop<7>(sx, sw, d, t0, acc);
        else if (ch.z == 9)  conv_loop<9>(sx, sw, d, t0, acc);
        else                 conv_loop<11>(sx, sw, d, t0, acc);

        // per-thread reduce over r, then warp reduce
        float mx[8], ct[8];
        #pragma unroll
        for (int q = 0; q < 8; q++) {
            float m  = acc[0][q];
            float c2 = acc[0][q] > 0.0f ? 1.0f : 0.0f;
            #pragma unroll
            for (int r = 1; r < 8; r++) {
                m = fmaxf(m, acc[r][q]);
                c2 += acc[r][q] > 0.0f ? 1.0f : 0.0f;
            }
            #pragma unroll
            for (int o = 16; o > 0; o >>= 1) {
                m  = fmaxf(m, __shfl_xor_sync(0xffffffffu, m, o));
                c2 += __shfl_xor_sync(0xffffffffu, c2, o);
            }
            mx[q] = m; ct[q] = c2;
        }
        if (lane == 0) {
            #pragma unroll
            for (int q = 0; q < 8; q++) {
                sred[warp][q][0] = mx[q];
                sred[warp][q][1] = ct[q];
            }
        }
        __syncthreads();
        if (threadIdx.x < CHUNK) {
            int q = threadIdx.x;
            if (q < ch.y) {
                float m  = sred[0][q][0];
                float c2 = sred[0][q][1];
                #pragma unroll
                for (int w = 1; w < 4; w++) {
                    m = fmaxf(m, sred[w][q][0]);
                    c2 += sred[w][q][1];
                }
                int orig = g_sorted[ch.x + q];
                float2 o;
                o.x = m;
                o.y = c2 * (1.0f / 1024.0f);
                *(float2*)(out + (long long)b * OUT_STRIDE + 2 * orig) = o;
            }
        }

        // advance item
        ci++;
        if (ci == nch) { ci = 0; b++; }
    }
}

// ---------------------------------------------------------------------------
// Launch
// ---------------------------------------------------------------------------
extern "C" void kernel_launch(void* const* d_in, const int* in_sizes, int n_in,
                              void* d_out, int out_size) {
    const float* x       = (const float*)d_in[0];
    const float* weights = (const float*)d_in[1];
    const float* biases  = (const float*)d_in[2];
    float* out = (float*)d_out;

    rng_kernel<<<1, 1>>>();
    group_kernel<<<1, 256>>>(weights);
    wt_kernel<<<MAXCHUNKS, 256>>>(weights, biases);

    int dev = 0, nsm = 148;
    cudaGetDevice(&dev);
    if (cudaDeviceGetAttribute(&nsm, cudaDevAttrMultiProcessorCount, dev) != cudaSuccess || nsm <= 0)
        nsm = 148;
    rocket_main<<<4 * nsm, 128>>>(x, out);
}

// round 2
// speedup vs baseline: 1.7889x; 1.7889x over previous
#include <cuda_runtime.h>
#include <cuda_bf16.h>
#include <stdint.h>

// ---------------------------------------------------------------------------
// Problem constants
// ---------------------------------------------------------------------------
#define N_KERNELS 10000
#define IN_CH 3
#define BATCH 64
#define T_LEN 1024
#define MAXK 11
#define W_STRIDE (IN_CH * MAXK)   // 33 floats per kernel
#define PADL 80                   // max pad = ((11-1)/2)*16 = 80
#define XPITCH (T_LEN + 2 * PADL) // 1184
#define NGROUPS 15
#define CHUNK 8
#define MAXCHUNKS 1266            // <= 10000/8 + 15
#define OUT_STRIDE (2 * N_KERNELS)

// ---------------------------------------------------------------------------
// Device-global scratch (no allocations allowed)
// ---------------------------------------------------------------------------
__device__ uint8_t g_didx[N_KERNELS];   // dilation index 0..4 from RNG
__device__ uint8_t g_kidx_rng[N_KERNELS];
__device__ uint8_t g_garr[N_KERNELS];   // group id 0..14
__device__ int     g_sorted[N_KERNELS]; // kernel ids sorted by group
__device__ int     g_nchunks;
__device__ int4    g_chunks[MAXCHUNKS]; // {start, count, k, d}
__device__ float   g_wT[MAXCHUNKS * 33 * CHUNK]; // [chunk][tap][8]
__device__ float   g_biasT[MAXCHUNKS * CHUNK];

__constant__ int c_dils[5] = {1, 2, 4, 8, 16};

// ---------------------------------------------------------------------------
// NumPy default_rng(0) reproduction: SeedSequence -> PCG64 (XSL-RR) -> Lemire
// ---------------------------------------------------------------------------
struct Pcg {
    unsigned long long shi, slo;  // 128-bit state
    unsigned long long ihi, ilo;  // 128-bit inc
    int has32;
    unsigned int buf;
};

__device__ __forceinline__ void pcg_step(Pcg &p) {
    const unsigned long long MH = 2549297995355413924ull;
    const unsigned long long ML = 4865540595714422341ull;
    unsigned long long nlo = p.slo * ML;
    unsigned long long nhi = __umul64hi(p.slo, ML) + p.shi * ML + p.slo * MH;
    unsigned long long alo = nlo + p.ilo;
    unsigned long long ahi = nhi + p.ihi + (alo < nlo ? 1ull : 0ull);
    p.slo = alo; p.shi = ahi;
}

__device__ __forceinline__ unsigned long long pcg_next64(Pcg &p) {
    pcg_step(p);
    unsigned int rot = (unsigned int)(p.shi >> 58);
    unsigned long long x = p.shi ^ p.slo;
    return (x >> rot) | (x << ((64u - rot) & 63u));
}

__device__ __forceinline__ unsigned int pcg_next32(Pcg &p) {
    if (p.has32) { p.has32 = 0; return p.buf; }
    unsigned long long v = pcg_next64(p);
    p.has32 = 1;
    p.buf = (unsigned int)(v >> 32);
    return (unsigned int)v;
}

// Lemire bounded sample over [0, excl) with NumPy's exact rejection logic
__device__ __forceinline__ unsigned int lemire32(Pcg &p, unsigned int excl) {
    unsigned long long m = (unsigned long long)pcg_next32(p) * (unsigned long long)excl;
    unsigned int leftover = (unsigned int)m;
    if (leftover < excl) {
        unsigned int thr = (unsigned int)(0u - excl) % excl;
        while (leftover < thr) {
            m = (unsigned long long)pcg_next32(p) * (unsigned long long)excl;
            leftover = (unsigned int)m;
        }
    }
    return (unsigned int)(m >> 32);
}

__device__ __forceinline__ unsigned int hashmix32(unsigned int v, unsigned int *hc) {
    v ^= *hc;
    *hc *= 0x931e8875u;
    v *= *hc;
    v ^= v >> 16;
    return v;
}

__device__ __forceinline__ unsigned int mix32(unsigned int x, unsigned int y) {
    unsigned int r = x * 0xca01f9ddu - y * 0x4973f715u;
    r ^= r >> 16;
    return r;
}

__global__ void rng_kernel() {
    if (threadIdx.x != 0 || blockIdx.x != 0) return;

    // SeedSequence(0): entropy = [0], pool_size = 4
    unsigned int pool[4];
    unsigned int hc = 0x43b0d7e5u;  // INIT_A
    for (int i = 0; i < 4; i++) pool[i] = hashmix32(0u, &hc);
    for (int s = 0; s < 4; s++)
        for (int d = 0; d < 4; d++)
            if (s != d) pool[d] = mix32(pool[d], hashmix32(pool[s], &hc));

    // generate_state(4, uint64) -> 8 uint32 words (little-endian pairs)
    unsigned int hb = 0x8b51f9ddu;  // INIT_B
    unsigned int w32[8];
    for (int i = 0; i < 8; i++) {
        unsigned int v = pool[i & 3];
        v ^= hb;
        hb *= 0x58f38dedu;  // MULT_B
        v *= hb;
        v ^= v >> 16;
        w32[i] = v;
    }
    unsigned long long s0 = (unsigned long long)w32[0] | ((unsigned long long)w32[1] << 32);
    unsigned long long s1 = (unsigned long long)w32[2] | ((unsigned long long)w32[3] << 32);
    unsigned long long s2 = (unsigned long long)w32[4] | ((unsigned long long)w32[5] << 32);
    unsigned long long s3 = (unsigned long long)w32[6] | ((unsigned long long)w32[7] << 32);

    Pcg p;
    p.shi = 0; p.slo = 0;
    p.ihi = (s2 << 1) | (s3 >> 63);
    p.ilo = (s3 << 1) | 1ull;
    p.has32 = 0; p.buf = 0;
    pcg_step(p);
    unsigned long long alo = p.slo + s1;
    p.shi = p.shi + s0 + (alo < p.slo ? 1ull : 0ull);
    p.slo = alo;
    pcg_step(p);

    for (int i = 0; i < N_KERNELS; i++) g_kidx_rng[i] = (uint8_t)lemire32(p, 3u);
    for (int i = 0; i < N_KERNELS; i++) g_didx[i]     = (uint8_t)lemire32(p, 5u);
}

// ---------------------------------------------------------------------------
// Group kernels by (k, d); counting sort; build chunk table
// ---------------------------------------------------------------------------
__global__ void group_kernel(const float* __restrict__ weights) {
    __shared__ int cnt[NGROUPS];
    __shared__ int off[NGROUPS + 1];
    __shared__ int scnt[NGROUPS];

    int tid = threadIdx.x;
    if (tid < NGROUPS) cnt[tid] = 0;
    __syncthreads();

    for (int i = tid; i < N_KERNELS; i += blockDim.x) {
        const float* w = weights + i * W_STRIDE;
        bool t11 = false, t9 = false;
        #pragma unroll
        for (int c = 0; c < 3; c++) {
            t11 |= (w[c * MAXK + 9] != 0.0f) | (w[c * MAXK + 10] != 0.0f);
            t9  |= (w[c * MAXK + 7] != 0.0f) | (w[c * MAXK + 8]  != 0.0f);
        }
        int kidx = t11 ? 2 : (t9 ? 1 : 0);
        int g = kidx * 5 + (int)g_didx[i];
        g_garr[i] = (uint8_t)g;
        atomicAdd(&cnt[g], 1);
    }
    __syncthreads();

    if (tid == 0) {
        off[0] = 0;
        for (int g = 0; g < NGROUPS; g++) off[g + 1] = off[g] + cnt[g];
        int nch = 0;
        for (int g = 0; g < NGROUPS; g++) {
            int ks = 7 + 2 * (g / 5);
            int d  = c_dils[g % 5];
            int n  = cnt[g];
            int base = off[g];
            for (int s = 0; s < n; s += CHUNK) {
                int4 ch;
                ch.x = base + s;
                ch.y = (n - s < CHUNK) ? (n - s) : CHUNK;
                ch.z = ks;
                ch.w = d;
                g_chunks[nch++] = ch;
            }
        }
        g_nchunks = nch;
        for (int g = 0; g < NGROUPS; g++) scnt[g] = off[g];
    }
    __syncthreads();

    for (int i = tid; i < N_KERNELS; i += blockDim.x) {
        int g = g_garr[i];
        int p = atomicAdd(&scnt[g], 1);
        g_sorted[p] = i;
    }
}

// ---------------------------------------------------------------------------
// Transpose weights into [chunk][tap(c*k+j)][8] layout + biases
// ---------------------------------------------------------------------------
__global__ void wt_kernel(const float* __restrict__ weights,
                          const float* __restrict__ biases) {
    int ci = blockIdx.x;
    if (ci >= g_nchunks) return;
    int4 ch = g_chunks[ci];
    int start = ch.x, count = ch.y, k = ch.z;
    int ntap = 3 * k;

    for (int idx = threadIdx.x; idx < 33 * CHUNK; idx += blockDim.x) {
        int q = idx & 7;
        int tap = idx >> 3;
        float v = 0.0f;
        if (q < count && tap < ntap) {
            int i = g_sorted[start + q];
            int c = tap / k;
            int j = tap - c * k;
            v = weights[i * W_STRIDE + c * MAXK + j];
        }
        g_wT[ci * (33 * CHUNK) + idx] = v;
    }
    if (threadIdx.x < CHUNK) {
        float b = 0.0f;
        if (threadIdx.x < count) b = biases[g_sorted[start + threadIdx.x]];
        g_biasT[ci * CHUNK + threadIdx.x] = b;
    }
}

// ---------------------------------------------------------------------------
// Main conv + max/ppv kernel — packed fma.rn.f32x2 (2 FMA/instr on Blackwell)
// ---------------------------------------------------------------------------
// acc[r][p] holds the packed pair of accumulators for kernels q=2p, q=2p+1
// at t-point r. Weights for a q-pair are adjacent in the [tap][8] layout, so
// they load directly as 64-bit lanes of an LDS.128. x is broadcast into both
// halves via one mov.b64 {x,x} per load (ALU pipe, far below its cap).
template <int K>
__device__ __forceinline__ void conv_loop(const float* __restrict__ sx,
                                          const float* __restrict__ sw,
                                          int d, int t0,
                                          unsigned long long acc[8][4]) {
    const int h = (K - 1) / 2;
    #pragma unroll
    for (int c = 0; c < 3; c++) {
        const float* xb = sx + c * XPITCH + PADL - h * d + t0;
        #pragma unroll
        for (int j = 0; j < K; j++) {
            const ulonglong2* wp = (const ulonglong2*)(sw + (c * K + j) * CHUNK);
            ulonglong2 w01 = wp[0];   // {w0,w1},{w2,w3}
            ulonglong2 w23 = wp[1];   // {w4,w5},{w6,w7}
            const float* xp = xb + j * d;
            #pragma unroll
            for (int r = 0; r < 8; r++) {
                float xv = xp[r * 32];
                unsigned long long xx;
                asm("mov.b64 %0, {%1, %1};" : "=l"(xx) : "f"(xv));
                asm("fma.rn.f32x2 %0, %1, %2, %0;" : "+l"(acc[r][0]) : "l"(xx), "l"(w01.x));
                asm("fma.rn.f32x2 %0, %1, %2, %0;" : "+l"(acc[r][1]) : "l"(xx), "l"(w01.y));
                asm("fma.rn.f32x2 %0, %1, %2, %0;" : "+l"(acc[r][2]) : "l"(xx), "l"(w23.x));
                asm("fma.rn.f32x2 %0, %1, %2, %0;" : "+l"(acc[r][3]) : "l"(xx), "l"(w23.y));
            }
        }
    }
}

__global__ void __launch_bounds__(128, 4)
rocket_main(const float* __restrict__ x, float* __restrict__ out) {
    __shared__ __align__(16) float sx[3 * XPITCH];
    __shared__ __align__(16) float sw[33 * CHUNK];
    __shared__ __align__(16) float sb[CHUNK];
    __shared__ float sred[4][CHUNK][2];

    const int nch = g_nchunks;
    const long long nit = (long long)nch * BATCH;
    const int nb = gridDim.x;
    long long s = (long long)blockIdx.x * nit / nb;
    long long e = (long long)(blockIdx.x + 1) * nit / nb;
    if (s >= e) return;

    int b  = (int)(s / nch);
    int ci = (int)(s - (long long)b * nch);
    int curb = -1;

    const int warp = threadIdx.x >> 5;
    const int lane = threadIdx.x & 31;
    const int t0 = warp * 256 + lane;

    for (long long it = s; it < e; it++) {
        if (b != curb) {
            __syncthreads();
            for (int idx = threadIdx.x; idx < 3 * XPITCH; idx += 128) sx[idx] = 0.0f;
            __syncthreads();
            for (int idx = threadIdx.x; idx < 3 * T_LEN; idx += 128) {
                int c = idx >> 10;
                int t = idx & (T_LEN - 1);
                sx[c * XPITCH + PADL + t] = x[b * 3 * T_LEN + idx];
            }
            curb = b;
        }
        __syncthreads();  // previous iteration fully done with sw/sred

        int4 ch = g_chunks[ci];
        for (int idx = threadIdx.x; idx < 33 * CHUNK; idx += 128)
            sw[idx] = g_wT[ci * (33 * CHUNK) + idx];
        if (threadIdx.x < CHUNK) sb[threadIdx.x] = g_biasT[ci * CHUNK + threadIdx.x];
        __syncthreads();

        // init packed accumulators with bias pairs
        unsigned long long acc[8][4];
        {
            const unsigned long long* sbp = (const unsigned long long*)sb;
            unsigned long long b0 = sbp[0], b1 = sbp[1], b2 = sbp[2], b3 = sbp[3];
            #pragma unroll
            for (int r = 0; r < 8; r++) {
                acc[r][0] = b0; acc[r][1] = b1; acc[r][2] = b2; acc[r][3] = b3;
            }
        }

        int d = ch.w;
        if (ch.z == 7)       conv_loop<7>(sx, sw, d, t0, acc);
        else if (ch.z == 9)  conv_loop<9>(sx, sw, d, t0, acc);
        else                 conv_loop<11>(sx, sw, d, t0, acc);

        // epilogue: per q-pair unpack, per-thread reduce over r, warp butterfly
        #pragma unroll
        for (int p = 0; p < 4; p++) {
            float lo[8], hi[8];
            #pragma unroll
            for (int r = 0; r < 8; r++) {
                asm("mov.b64 {%0, %1}, %2;" : "=f"(lo[r]), "=f"(hi[r]) : "l"(acc[r][p]));
            }
            float m0 = lo[0], m1 = hi[0];
            float c0 = lo[0] > 0.0f ? 1.0f : 0.0f;
            float c1 = hi[0] > 0.0f ? 1.0f : 0.0f;
            #pragma unroll
            for (int r = 1; r < 8; r++) {
                m0 = fmaxf(m0, lo[r]);
                m1 = fmaxf(m1, hi[r]);
                c0 += lo[r] > 0.0f ? 1.0f : 0.0f;
                c1 += hi[r] > 0.0f ? 1.0f : 0.0f;
            }
            #pragma unroll
            for (int o = 16; o > 0; o >>= 1) {
                m0 = fmaxf(m0, __shfl_xor_sync(0xffffffffu, m0, o));
                m1 = fmaxf(m1, __shfl_xor_sync(0xffffffffu, m1, o));
                c0 += __shfl_xor_sync(0xffffffffu, c0, o);
                c1 += __shfl_xor_sync(0xffffffffu, c1, o);
            }
            if (lane == 0) {
                sred[warp][2 * p][0] = m0;
                sred[warp][2 * p][1] = c0;
                sred[warp][2 * p + 1][0] = m1;
                sred[warp][2 * p + 1][1] = c1;
            }
        }
        __syncthreads();
        if (threadIdx.x < CHUNK) {
            int q = threadIdx.x;
            if (q < ch.y) {
                float m  = sred[0][q][0];
                float c2 = sred[0][q][1];
                #pragma unroll
                for (int w = 1; w < 4; w++) {
                    m = fmaxf(m, sred[w][q][0]);
                    c2 += sred[w][q][1];
                }
                int orig = g_sorted[ch.x + q];
                float2 o;
                o.x = m;
                o.y = c2 * (1.0f / 1024.0f);
                *(float2*)(out + (long long)b * OUT_STRIDE + 2 * orig) = o;
            }
        }

        ci++;
        if (ci == nch) { ci = 0; b++; }
    }
}

// ---------------------------------------------------------------------------
// Launch
// ---------------------------------------------------------------------------
extern "C" void kernel_launch(void* const* d_in, const int* in_sizes, int n_in,
                              void* d_out, int out_size) {
    const float* x       = (const float*)d_in[0];
    const float* weights = (const float*)d_in[1];
    const float* biases  = (const float*)d_in[2];
    float* out = (float*)d_out;

    rng_kernel<<<1, 1>>>();
    group_kernel<<<1, 256>>>(weights);
    wt_kernel<<<MAXCHUNKS, 256>>>(weights, biases);

    int dev = 0, nsm = 148;
    cudaGetDevice(&dev);
    if (cudaDeviceGetAttribute(&nsm, cudaDevAttrMultiProcessorCount, dev) != cudaSuccess || nsm <= 0)
        nsm = 148;
    rocket_main<<<4 * nsm, 128>>>(x, out);
}

// round 3
// speedup vs baseline: 3.5253x; 1.9706x over previous
#include <cuda_runtime.h>
#include <cuda_bf16.h>
#include <stdint.h>

typedef unsigned long long ull;

// ---------------------------------------------------------------------------
// Problem constants
// ---------------------------------------------------------------------------
#define N_KERNELS 10000
#define IN_CH 3
#define BATCH 64
#define T_LEN 1024
#define MAXK 11
#define W_STRIDE (IN_CH * MAXK)   // 33 floats per kernel
#define PADL 80                   // max pad = ((11-1)/2)*16 = 80
#define XPITCH (T_LEN + 2 * PADL) // 1184
#define NGROUPS 15
#define CHUNK 8
#define WROW 16                   // 8 kernels x duplicated pair
#define MAXCHUNKS 1266
#define OUT_STRIDE (2 * N_KERNELS)

// ---------------------------------------------------------------------------
// Device-global scratch (no allocations allowed)
// ---------------------------------------------------------------------------
__device__ uint8_t g_didx[N_KERNELS];   // dilation index 0..4 from RNG
__device__ uint8_t g_garr[N_KERNELS];   // group id 0..14
__device__ int     g_sorted[N_KERNELS]; // kernel ids sorted by group
__device__ int     g_nchunks;
__device__ int4    g_chunks[MAXCHUNKS]; // {start, count, k, d}
__device__ float   g_wT[MAXCHUNKS * 33 * WROW]; // [chunk][tap][16] dup pairs
__device__ float   g_biasT[MAXCHUNKS * CHUNK];
__device__ int     g_rng_bad;

__constant__ int c_dils[5] = {1, 2, 4, 8, 16};

// ---------------------------------------------------------------------------
// NumPy default_rng(0): SeedSequence -> PCG64 (XSL-RR) -> Lemire
// ---------------------------------------------------------------------------
#define PCG_MH 2549297995355413924ull
#define PCG_ML 4865540595714422341ull

struct Pcg {
    ull shi, slo;  // 128-bit state
    ull ihi, ilo;  // 128-bit inc
    int has32;
    unsigned int buf;
};

__device__ __forceinline__ void mul128(ull alo, ull ahi, ull blo, ull bhi,
                                       ull &rlo, ull &rhi) {
    rlo = alo * blo;
    rhi = __umul64hi(alo, blo) + alo * bhi + ahi * blo;
}

__device__ __forceinline__ void add128(ull &alo, ull &ahi, ull blo, ull bhi) {
    ull t = alo + blo;
    ahi = ahi + bhi + (t < alo ? 1ull : 0ull);
    alo = t;
}

__device__ __forceinline__ void pcg_step(Pcg &p) {
    ull nlo, nhi;
    mul128(p.slo, p.shi, PCG_ML, PCG_MH, nlo, nhi);
    add128(nlo, nhi, p.ilo, p.ihi);
    p.slo = nlo; p.shi = nhi;
}

__device__ __forceinline__ ull pcg_out(ull slo, ull shi) {
    unsigned int rot = (unsigned int)(shi >> 58);
    ull x = shi ^ slo;
    return (x >> rot) | (x << ((64u - rot) & 63u));
}

__device__ __forceinline__ ull pcg_next64(Pcg &p) {
    pcg_step(p);
    return pcg_out(p.slo, p.shi);
}

__device__ __forceinline__ unsigned int pcg_next32(Pcg &p) {
    if (p.has32) { p.has32 = 0; return p.buf; }
    ull v = pcg_next64(p);
    p.has32 = 1;
    p.buf = (unsigned int)(v >> 32);
    return (unsigned int)v;
}

__device__ __forceinline__ unsigned int lemire32(Pcg &p, unsigned int excl) {
    ull m = (ull)pcg_next32(p) * (ull)excl;
    unsigned int leftover = (unsigned int)m;
    if (leftover < excl) {
        unsigned int thr = (unsigned int)(0u - excl) % excl;
        while (leftover < thr) {
            m = (ull)pcg_next32(p) * (ull)excl;
            leftover = (unsigned int)m;
        }
    }
    return (unsigned int)(m >> 32);
}

__device__ __forceinline__ unsigned int hashmix32(unsigned int v, unsigned int *hc) {
    v ^= *hc;
    *hc *= 0x931e8875u;
    v *= *hc;
    v ^= v >> 16;
    return v;
}

__device__ __forceinline__ unsigned int mix32(unsigned int x, unsigned int y) {
    unsigned int r = x * 0xca01f9ddu - y * 0x4973f715u;
    r ^= r >> 16;
    return r;
}

// Build the seeded PCG base state (state BEFORE the first output step)
__device__ void pcg_seed0(Pcg &p) {
    unsigned int pool[4];
    unsigned int hc = 0x43b0d7e5u;
    for (int i = 0; i < 4; i++) pool[i] = hashmix32(0u, &hc);
    for (int s = 0; s < 4; s++)
        for (int d = 0; d < 4; d++)
            if (s != d) pool[d] = mix32(pool[d], hashmix32(pool[s], &hc));
    unsigned int hb = 0x8b51f9ddu;
    unsigned int w32[8];
    for (int i = 0; i < 8; i++) {
        unsigned int v = pool[i & 3];
        v ^= hb;
        hb *= 0x58f38dedu;
        v *= hb;
        v ^= v >> 16;
        w32[i] = v;
    }
    ull s0 = (ull)w32[0] | ((ull)w32[1] << 32);
    ull s1 = (ull)w32[2] | ((ull)w32[3] << 32);
    ull s2 = (ull)w32[4] | ((ull)w32[5] << 32);
    ull s3 = (ull)w32[6] | ((ull)w32[7] << 32);

    p.shi = 0; p.slo = 0;
    p.ihi = (s2 << 1) | (s3 >> 63);
    p.ilo = (s3 << 1) | 1ull;
    p.has32 = 0; p.buf = 0;
    pcg_step(p);
    add128(p.slo, p.shi, s1, s0);
    pcg_step(p);
}

__global__ void rng_reset() { g_rng_bad = 0; }

// Parallel RNG: thread n computes 64-bit output n via LCG jump-ahead.
// Output n = XSL-RR(advance(base, n+1)). 32-bit draws 2n(lo), 2n+1(hi).
// Draws [0,10000) are k-indices (unused; k derived from weight mask),
// draws [10000,20000) are dilation indices, bound 5.
// Lemire rejection for bounds 3/5 happens iff a raw 32-bit draw == 0
// (threshold = 2^32 mod {3,5} = 1); flag it and let the sequential
// fallback redo everything exactly.
__global__ void rng_par() {
    int n = blockIdx.x * blockDim.x + threadIdx.x;
    if (n >= N_KERNELS) return;

    Pcg p;
    pcg_seed0(p);

    // advance base by delta = n+1:  state' = am*state + ap
    ull delta = (ull)(n + 1);
    ull am_lo = 1, am_hi = 0, ap_lo = 0, ap_hi = 0;
    ull cm_lo = PCG_ML, cm_hi = PCG_MH;
    ull cp_lo = p.ilo, cp_hi = p.ihi;
    while (delta) {
        if (delta & 1) {
            ull tlo, thi;
            mul128(am_lo, am_hi, cm_lo, cm_hi, tlo, thi);
            am_lo = tlo; am_hi = thi;
            mul128(ap_lo, ap_hi, cm_lo, cm_hi, tlo, thi);
            add128(tlo, thi, cp_lo, cp_hi);
            ap_lo = tlo; ap_hi = thi;
        }
        ull e_lo = cm_lo + 1;
        ull e_hi = cm_hi + (e_lo == 0 ? 1ull : 0ull);
        ull tlo, thi;
        mul128(e_lo, e_hi, cp_lo, cp_hi, tlo, thi);
        cp_lo = tlo; cp_hi = thi;
        mul128(cm_lo, cm_hi, cm_lo, cm_hi, tlo, thi);
        cm_lo = tlo; cm_hi = thi;
        delta >>= 1;
    }
    ull slo, shi;
    mul128(p.slo, p.shi, am_lo, am_hi, slo, shi);
    add128(slo, shi, ap_lo, ap_hi);

    ull out = pcg_out(slo, shi);
    unsigned int lo = (unsigned int)out;
    unsigned int hi = (unsigned int)(out >> 32);
    if (lo == 0u || hi == 0u) atomicOr(&g_rng_bad, 1);

    if (n >= N_KERNELS / 2) {
        int j = 2 * n - N_KERNELS;
        g_didx[j]     = (uint8_t)(((ull)lo * 5ull) >> 32);
        g_didx[j + 1] = (uint8_t)(((ull)hi * 5ull) >> 32);
    }
}

// Exact sequential fallback, only runs if a rejection-region draw occurred.
__global__ void rng_seq() {
    if (threadIdx.x != 0 || blockIdx.x != 0) return;
    if (g_rng_bad == 0) return;
    Pcg p;
    pcg_seed0(p);
    for (int i = 0; i < N_KERNELS; i++) (void)lemire32(p, 3u);
    for (int i = 0; i < N_KERNELS; i++) g_didx[i] = (uint8_t)lemire32(p, 5u);
}

// ---------------------------------------------------------------------------
// Group kernels by (k, d); counting sort; build chunk table
// ---------------------------------------------------------------------------
__global__ void group_kernel(const float* __restrict__ weights) {
    __shared__ int cnt[NGROUPS];
    __shared__ int off[NGROUPS + 1];
    __shared__ int scnt[NGROUPS];

    int tid = threadIdx.x;
    if (tid < NGROUPS) cnt[tid] = 0;
    __syncthreads();

    for (int i = tid; i < N_KERNELS; i += blockDim.x) {
        const float* w = weights + i * W_STRIDE;
        bool t11 = false, t9 = false;
        #pragma unroll
        for (int c = 0; c < 3; c++) {
            t11 |= (w[c * MAXK + 9] != 0.0f) | (w[c * MAXK + 10] != 0.0f);
            t9  |= (w[c * MAXK + 7] != 0.0f) | (w[c * MAXK + 8]  != 0.0f);
        }
        int kidx = t11 ? 2 : (t9 ? 1 : 0);
        int g = kidx * 5 + (int)g_didx[i];
        g_garr[i] = (uint8_t)g;
        atomicAdd(&cnt[g], 1);
    }
    __syncthreads();

    if (tid == 0) {
        off[0] = 0;
        for (int g = 0; g < NGROUPS; g++) off[g + 1] = off[g] + cnt[g];
        int nch = 0;
        for (int g = 0; g < NGROUPS; g++) {
            int ks = 7 + 2 * (g / 5);
            int d  = c_dils[g % 5];
            int n  = cnt[g];
            int base = off[g];
            for (int s = 0; s < n; s += CHUNK) {
                int4 ch;
                ch.x = base + s;
                ch.y = (n - s < CHUNK) ? (n - s) : CHUNK;
                ch.z = ks;
                ch.w = d;
                g_chunks[nch++] = ch;
            }
        }
        g_nchunks = nch;
        for (int g = 0; g < NGROUPS; g++) scnt[g] = off[g];
    }
    __syncthreads();

    for (int i = tid; i < N_KERNELS; i += blockDim.x) {
        int g = g_garr[i];
        int p = atomicAdd(&scnt[g], 1);
        g_sorted[p] = i;
    }
}

// ---------------------------------------------------------------------------
// Transpose weights into [chunk][tap][16] with duplicated pairs {w_q, w_q}
// ---------------------------------------------------------------------------
__global__ void wt_kernel(const float* __restrict__ weights,
                          const float* __restrict__ biases) {
    int ci = blockIdx.x;
    if (ci >= g_nchunks) return;
    int4 ch = g_chunks[ci];
    int start = ch.x, count = ch.y, k = ch.z;
    int ntap = 3 * k;

    for (int idx = threadIdx.x; idx < 33 * WROW; idx += blockDim.x) {
        int tap = idx >> 4;
        int q = (idx >> 1) & 7;
        float v = 0.0f;
        if (q < count && tap < ntap) {
            int i = g_sorted[start + q];
            int c = tap / k;
            int j = tap - c * k;
            v = weights[i * W_STRIDE + c * MAXK + j];
        }
        g_wT[ci * (33 * WROW) + idx] = v;
    }
    if (threadIdx.x < CHUNK) {
        float b = 0.0f;
        if (threadIdx.x < count) b = biases[g_sorted[start + threadIdx.x]];
        g_biasT[ci * CHUNK + threadIdx.x] = b;
    }
}

// ---------------------------------------------------------------------------
// Main conv kernel.
// f32x2 lanes pack two adjacent t-points of the SAME kernel q.
// acc[rp][q]: t = warp*256 + lane*2 + 64*rp + {0,1}.
// Weights arrive pre-duplicated {w,w} -> 4x LDS.128 broadcast per tap.
// x arrives as 4x aligned LDS.64 per tap (even d); d==1 uses compile-time
// scalar-pack for odd-parity taps.
// ---------------------------------------------------------------------------
#define FMA2(a, x, w) asm("fma.rn.f32x2 %0, %1, %2, %0;" : "+l"(a) : "l"(x), "l"(w))

__device__ __forceinline__ void load_wrow(const float* __restrict__ wrow, ull w[8]) {
    ulonglong2 t;
    t = *(const ulonglong2*)(wrow + 0);  w[0] = t.x; w[1] = t.y;
    t = *(const ulonglong2*)(wrow + 4);  w[2] = t.x; w[3] = t.y;
    t = *(const ulonglong2*)(wrow + 8);  w[4] = t.x; w[5] = t.y;
    t = *(const ulonglong2*)(wrow + 12); w[6] = t.x; w[7] = t.y;
}

template <int K>
__device__ __forceinline__ void conv_vec(const float* __restrict__ sx,
                                         const float* __restrict__ sw,
                                         int d, int t0, ull acc[4][8]) {
    const int h = (K - 1) / 2;
    #pragma unroll
    for (int c = 0; c < 3; c++) {
        const float* xb = sx + c * XPITCH + PADL - h * d + t0;
        #pragma unroll
        for (int j = 0; j < K; j++) {
            ull w[8];
            load_wrow(sw + (c * K + j) * WROW, w);
            const float* xp = xb + j * d;
            ull xx[4];
            #pragma unroll
            for (int rp = 0; rp < 4; rp++)
                xx[rp] = *(const ull*)(xp + rp * 64);
            #pragma unroll
            for (int rp = 0; rp < 4; rp++) {
                #pragma unroll
                for (int q = 0; q < 8; q++) FMA2(acc[rp][q], xx[rp], w[q]);
            }
        }
    }
}

template <int K>
__device__ __forceinline__ void conv_d1(const float* __restrict__ sx,
                                        const float* __restrict__ sw,
                                        int t0, ull acc[4][8]) {
    const int h = (K - 1) / 2;
    #pragma unroll
    for (int c = 0; c < 3; c++) {
        const float* xb = sx + c * XPITCH + PADL - h + t0;
        #pragma unroll
        for (int j = 0; j < K; j++) {
            ull w[8];
            load_wrow(sw + (c * K + j) * WROW, w);
            const float* xp = xb + j;
            ull xx[4];
            if ((j - h) & 1) {
                #pragma unroll
                for (int rp = 0; rp < 4; rp++) {
                    float a = xp[rp * 64];
                    float b = xp[rp * 64 + 1];
                    asm("mov.b64 %0, {%1, %2};" : "=l"(xx[rp]) : "f"(a), "f"(b));
                }
            } else {
                #pragma unroll
                for (int rp = 0; rp < 4; rp++)
                    xx[rp] = *(const ull*)(xp + rp * 64);
            }
            #pragma unroll
            for (int rp = 0; rp < 4; rp++) {
                #pragma unroll
                for (int q = 0; q < 8; q++) FMA2(acc[rp][q], xx[rp], w[q]);
            }
        }
    }
}

__global__ void __launch_bounds__(128, 4)
rocket_main(const float* __restrict__ x, float* __restrict__ out) {
    __shared__ __align__(16) float sx[3 * XPITCH];
    __shared__ __align__(16) float sw[33 * WROW];
    __shared__ __align__(16) float sb[CHUNK];
    __shared__ float sred[4][CHUNK][2];

    const int nch = g_nchunks;
    const long long nit = (long long)nch * BATCH;
    const int nb = gridDim.x;
    long long s = (long long)blockIdx.x * nit / nb;
    long long e = (long long)(blockIdx.x + 1) * nit / nb;
    if (s >= e) return;

    int b  = (int)(s / nch);
    int ci = (int)(s - (long long)b * nch);
    int curb = -1;

    const int warp = threadIdx.x >> 5;
    const int lane = threadIdx.x & 31;
    const int t0 = warp * 256 + lane * 2;

    for (long long it = s; it < e; it++) {
        if (b != curb) {
            __syncthreads();
            for (int idx = threadIdx.x; idx < 3 * XPITCH; idx += 128) sx[idx] = 0.0f;
            __syncthreads();
            for (int idx = threadIdx.x; idx < 3 * T_LEN; idx += 128) {
                int c = idx >> 10;
                int t = idx & (T_LEN - 1);
                sx[c * XPITCH + PADL + t] = x[b * 3 * T_LEN + idx];
            }
            curb = b;
        }
        __syncthreads();  // previous iteration fully done with sw/sred

        int4 ch = g_chunks[ci];
        for (int idx = threadIdx.x; idx < 33 * WROW; idx += 128)
            sw[idx] = g_wT[ci * (33 * WROW) + idx];
        if (threadIdx.x < CHUNK) sb[threadIdx.x] = g_biasT[ci * CHUNK + threadIdx.x];
        __syncthreads();

        // init packed accumulators with {bias,bias}
        ull acc[4][8];
        {
            ull bp[8];
            #pragma unroll
            for (int q = 0; q < 8; q++) {
                float bv = sb[q];
                asm("mov.b64 %0, {%1, %1};" : "=l"(bp[q]) : "f"(bv));
            }
            #pragma unroll
            for (int rp = 0; rp < 4; rp++)
                #pragma unroll
                for (int q = 0; q < 8; q++) acc[rp][q] = bp[q];
        }

        int d = ch.w;
        if (d == 1) {
            if (ch.z == 7)       conv_d1<7>(sx, sw, t0, acc);
            else if (ch.z == 9)  conv_d1<9>(sx, sw, t0, acc);
            else                 conv_d1<11>(sx, sw, t0, acc);
        } else {
            if (ch.z == 7)       conv_vec<7>(sx, sw, d, t0, acc);
            else if (ch.z == 9)  conv_vec<9>(sx, sw, d, t0, acc);
            else                 conv_vec<11>(sx, sw, d, t0, acc);
        }

        // epilogue: per kernel q, reduce 4 packed pairs -> warp butterfly
        #pragma unroll
        for (int q = 0; q < 8; q++) {
            float lo[4], hi[4];
            #pragma unroll
            for (int rp = 0; rp < 4; rp++)
                asm("mov.b64 {%0, %1}, %2;" : "=f"(lo[rp]), "=f"(hi[rp]) : "l"(acc[rp][q]));
            float m = fmaxf(fmaxf(fmaxf(lo[0], hi[0]), fmaxf(lo[1], hi[1])),
                            fmaxf(fmaxf(lo[2], hi[2]), fmaxf(lo[3], hi[3])));
            float c2 = 0.0f;
            #pragma unroll
            for (int rp = 0; rp < 4; rp++) {
                c2 += lo[rp] > 0.0f ? 1.0f : 0.0f;
                c2 += hi[rp] > 0.0f ? 1.0f : 0.0f;
            }
            #pragma unroll
            for (int o = 16; o > 0; o >>= 1) {
                m  = fmaxf(m, __shfl_xor_sync(0xffffffffu, m, o));
                c2 += __shfl_xor_sync(0xffffffffu, c2, o);
            }
            if (lane == 0) {
                sred[warp][q][0] = m;
                sred[warp][q][1] = c2;
            }
        }
        __syncthreads();
        if (threadIdx.x < CHUNK) {
            int q = threadIdx.x;
            if (q < ch.y) {
                float m  = sred[0][q][0];
                float c2 = sred[0][q][1];
                #pragma unroll
                for (int w = 1; w < 4; w++) {
                    m = fmaxf(m, sred[w][q][0]);
                    c2 += sred[w][q][1];
                }
                int orig = g_sorted[ch.x + q];
                float2 o;
                o.x = m;
                o.y = c2 * (1.0f / 1024.0f);
                *(float2*)(out + (long long)b * OUT_STRIDE + 2 * orig) = o;
            }
        }

        ci++;
        if (ci == nch) { ci = 0; b++; }
    }
}

// ---------------------------------------------------------------------------
// Launch
// ---------------------------------------------------------------------------
extern "C" void kernel_launch(void* const* d_in, const int* in_sizes, int n_in,
                              void* d_out, int out_size) {
    const float* x       = (const float*)d_in[0];
    const float* weights = (const float*)d_in[1];
    const float* biases  = (const float*)d_in[2];
    float* out = (float*)d_out;

    rng_reset<<<1, 1>>>();
    rng_par<<<(N_KERNELS + 255) / 256, 256>>>();
    rng_seq<<<1, 1>>>();
    group_kernel<<<1, 256>>>(weights);
    wt_kernel<<<MAXCHUNKS, 256>>>(weights, biases);

    int dev = 0, nsm = 148;
    cudaGetDevice(&dev);
    if (cudaDeviceGetAttribute(&nsm, cudaDevAttrMultiProcessorCount, dev) != cudaSuccess || nsm <= 0)
        nsm = 148;
    rocket_main<<<4 * nsm, 128>>>(x, out);
}

// round 5
// speedup vs baseline: 3.5946x; 1.0197x over previous
#include <cuda_runtime.h>
#include <cuda_bf16.h>
#include <stdint.h>

typedef unsigned long long ull;

// ---------------------------------------------------------------------------
// Problem constants
// ---------------------------------------------------------------------------
#define N_KERNELS 10000
#define IN_CH 3
#define BATCH 64
#define T_LEN 1024
#define MAXK 11
#define W_STRIDE (IN_CH * MAXK)   // 33 floats per kernel
#define PADL 80                   // max pad = ((11-1)/2)*16 = 80
#define XPITCH (T_LEN + 2 * PADL) // 1184
#define NGROUPS 15
#define CHUNK 8
#define WROW 16                   // 8 kernels x duplicated pair
#define MAXCHUNKS 1266
#define OUT_STRIDE (2 * N_KERNELS)

// ---------------------------------------------------------------------------
// Device-global scratch (no allocations allowed)
// ---------------------------------------------------------------------------
__device__ uint8_t g_kidx[N_KERNELS];   // ksize index 0..2 from RNG
__device__ uint8_t g_didx[N_KERNELS];   // dilation index 0..4 from RNG
__device__ uint8_t g_garr[N_KERNELS];   // group id 0..14
__device__ int     g_cnt[NGROUPS];
__device__ int     g_scnt[NGROUPS];
__device__ int     g_sorted[N_KERNELS]; // kernel ids sorted by group
__device__ int     g_nchunks;
__device__ int4    g_chunks[MAXCHUNKS]; // {start, count, k, d}
__device__ float   g_wT[MAXCHUNKS * 33 * WROW]; // [chunk][tap][16] dup pairs
__device__ float   g_biasT[MAXCHUNKS * CHUNK];
__device__ int     g_rng_bad;

__constant__ int c_dils[5] = {1, 2, 4, 8, 16};

// ---------------------------------------------------------------------------
// NumPy default_rng(0): SeedSequence -> PCG64 (XSL-RR) -> Lemire
// ---------------------------------------------------------------------------
#define PCG_MH 2549297995355413924ull
#define PCG_ML 4865540595714422341ull

struct Pcg {
    ull shi, slo;  // 128-bit state
    ull ihi, ilo;  // 128-bit inc
    int has32;
    unsigned int buf;
};

__device__ __forceinline__ void mul128(ull alo, ull ahi, ull blo, ull bhi,
                                       ull &rlo, ull &rhi) {
    rlo = alo * blo;
    rhi = __umul64hi(alo, blo) + alo * bhi + ahi * blo;
}

__device__ __forceinline__ void add128(ull &alo, ull &ahi, ull blo, ull bhi) {
    ull t = alo + blo;
    ahi = ahi + bhi + (t < alo ? 1ull : 0ull);
    alo = t;
}

__device__ __forceinline__ void pcg_step(Pcg &p) {
    ull nlo, nhi;
    mul128(p.slo, p.shi, PCG_ML, PCG_MH, nlo, nhi);
    add128(nlo, nhi, p.ilo, p.ihi);
    p.slo = nlo; p.shi = nhi;
}

__device__ __forceinline__ ull pcg_out(ull slo, ull shi) {
    unsigned int rot = (unsigned int)(shi >> 58);
    ull x = shi ^ slo;
    return (x >> rot) | (x << ((64u - rot) & 63u));
}

__device__ __forceinline__ ull pcg_next64(Pcg &p) {
    pcg_step(p);
    return pcg_out(p.slo, p.shi);
}

__device__ __forceinline__ unsigned int pcg_next32(Pcg &p) {
    if (p.has32) { p.has32 = 0; return p.buf; }
    ull v = pcg_next64(p);
    p.has32 = 1;
    p.buf = (unsigned int)(v >> 32);
    return (unsigned int)v;
}

__device__ __forceinline__ unsigned int lemire32(Pcg &p, unsigned int excl) {
    ull m = (ull)pcg_next32(p) * (ull)excl;
    unsigned int leftover = (unsigned int)m;
    if (leftover < excl) {
        unsigned int thr = (unsigned int)(0u - excl) % excl;
        while (leftover < thr) {
            m = (ull)pcg_next32(p) * (ull)excl;
            leftover = (unsigned int)m;
        }
    }
    return (unsigned int)(m >> 32);
}

__device__ __forceinline__ unsigned int hashmix32(unsigned int v, unsigned int *hc) {
    v ^= *hc;
    *hc *= 0x931e8875u;
    v *= *hc;
    v ^= v >> 16;
    return v;
}

__device__ __forceinline__ unsigned int mix32(unsigned int x, unsigned int y) {
    unsigned int r = x * 0xca01f9ddu - y * 0x4973f715u;
    r ^= r >> 16;
    return r;
}

// Build the seeded PCG base state (state BEFORE the first output step)
__device__ void pcg_seed0(Pcg &p) {
    unsigned int pool[4];
    unsigned int hc = 0x43b0d7e5u;
    for (int i = 0; i < 4; i++) pool[i] = hashmix32(0u, &hc);
    for (int s = 0; s < 4; s++)
        for (int d = 0; d < 4; d++)
            if (s != d) pool[d] = mix32(pool[d], hashmix32(pool[s], &hc));
    unsigned int hb = 0x8b51f9ddu;
    unsigned int w32[8];
    for (int i = 0; i < 8; i++) {
        unsigned int v = pool[i & 3];
        v ^= hb;
        hb *= 0x58f38dedu;
        v *= hb;
        v ^= v >> 16;
        w32[i] = v;
    }
    ull s0 = (ull)w32[0] | ((ull)w32[1] << 32);
    ull s1 = (ull)w32[2] | ((ull)w32[3] << 32);
    ull s2 = (ull)w32[4] | ((ull)w32[5] << 32);
    ull s3 = (ull)w32[6] | ((ull)w32[7] << 32);

    p.shi = 0; p.slo = 0;
    p.ihi = (s2 << 1) | (s3 >> 63);
    p.ilo = (s3 << 1) | 1ull;
    p.has32 = 0; p.buf = 0;
    pcg_step(p);
    add128(p.slo, p.shi, s1, s0);
    pcg_step(p);
}

__global__ void rng_reset() {
    g_rng_bad = 0;
    for (int g = 0; g < NGROUPS; g++) g_cnt[g] = 0;
}

// Parallel RNG: thread n computes 64-bit output n via LCG jump-ahead.
// 32-bit draws 2n (lo), 2n+1 (hi). Draws [0,10000): k-index (bound 3);
// draws [10000,20000): dilation index (bound 5). Lemire rejection for
// bounds 3/5 happens iff a raw 32-bit draw == 0 (threshold 1); flag and
// fall back to the exact sequential kernel in that (p~5e-6) case.
__global__ void rng_par() {
    int n = blockIdx.x * blockDim.x + threadIdx.x;
    if (n >= N_KERNELS) return;

    Pcg p;
    pcg_seed0(p);

    // advance base by delta = n+1:  state' = am*state + ap
    ull delta = (ull)(n + 1);
    ull am_lo = 1, am_hi = 0, ap_lo = 0, ap_hi = 0;
    ull cm_lo = PCG_ML, cm_hi = PCG_MH;
    ull cp_lo = p.ilo, cp_hi = p.ihi;
    while (delta) {
        if (delta & 1) {
            ull tlo, thi;
            mul128(am_lo, am_hi, cm_lo, cm_hi, tlo, thi);
            am_lo = tlo; am_hi = thi;
            mul128(ap_lo, ap_hi, cm_lo, cm_hi, tlo, thi);
            add128(tlo, thi, cp_lo, cp_hi);
            ap_lo = tlo; ap_hi = thi;
        }
        ull e_lo = cm_lo + 1;
        ull e_hi = cm_hi + (e_lo == 0 ? 1ull : 0ull);
        ull tlo, thi;
        mul128(e_lo, e_hi, cp_lo, cp_hi, tlo, thi);
        cp_lo = tlo; cp_hi = thi;
        mul128(cm_lo, cm_hi, cm_lo, cm_hi, tlo, thi);
        cm_lo = tlo; cm_hi = thi;
        delta >>= 1;
    }
    ull slo, shi;
    mul128(p.slo, p.shi, am_lo, am_hi, slo, shi);
    add128(slo, shi, ap_lo, ap_hi);

    ull out = pcg_out(slo, shi);
    unsigned int lo = (unsigned int)out;
    unsigned int hi = (unsigned int)(out >> 32);
    if (lo == 0u || hi == 0u) atomicOr(&g_rng_bad, 1);

    if (n < N_KERNELS / 2) {
        int j = 2 * n;
        g_kidx[j]     = (uint8_t)(((ull)lo * 3ull) >> 32);
        g_kidx[j + 1] = (uint8_t)(((ull)hi * 3ull) >> 32);
    } else {
        int j = 2 * n - N_KERNELS;
        g_didx[j]     = (uint8_t)(((ull)lo * 5ull) >> 32);
        g_didx[j + 1] = (uint8_t)(((ull)hi * 5ull) >> 32);
    }
}

// Exact sequential fallback, only runs if a rejection-region draw occurred.
__global__ void rng_seq() {
    if (threadIdx.x != 0 || blockIdx.x != 0) return;
    if (g_rng_bad == 0) return;
    Pcg p;
    pcg_seed0(p);
    for (int i = 0; i < N_KERNELS; i++) g_kidx[i] = (uint8_t)lemire32(p, 3u);
    for (int i = 0; i < N_KERNELS; i++) g_didx[i] = (uint8_t)lemire32(p, 5u);
}

// ---------------------------------------------------------------------------
// Parallel grouping: histogram -> offsets/chunks -> scatter
// (within-group order is arbitrary; outputs are per-kernel independent)
// ---------------------------------------------------------------------------
__global__ void hist_kernel() {
    int i = blockIdx.x * blockDim.x + threadIdx.x;
    if (i >= N_KERNELS) return;
    int g = (int)g_kidx[i] * 5 + (int)g_didx[i];
    g_garr[i] = (uint8_t)g;
    atomicAdd(&g_cnt[g], 1);
}

__global__ void offs_kernel() {
    if (threadIdx.x != 0) return;
    int off = 0;
    int nch = 0;
    for (int g = 0; g < NGROUPS; g++) {
        int ks = 7 + 2 * (g / 5);
        int d  = c_dils[g % 5];
        int n  = g_cnt[g];
        g_scnt[g] = off;
        for (int s = 0; s < n; s += CHUNK) {
            int4 ch;
            ch.x = off + s;
            ch.y = (n - s < CHUNK) ? (n - s) : CHUNK;
            ch.z = ks;
            ch.w = d;
            g_chunks[nch++] = ch;
        }
        off += n;
    }
    g_nchunks = nch;
}

__global__ void scatter_kernel() {
    int i = blockIdx.x * blockDim.x + threadIdx.x;
    if (i >= N_KERNELS) return;
    int g = g_garr[i];
    int p = atomicAdd(&g_scnt[g], 1);
    g_sorted[p] = i;
}

// ---------------------------------------------------------------------------
// Transpose weights into [chunk][tap][16] with duplicated pairs {w_q, w_q}
// ---------------------------------------------------------------------------
__global__ void wt_kernel(const float* __restrict__ weights,
                          const float* __restrict__ biases) {
    int ci = blockIdx.x;
    if (ci >= g_nchunks) return;
    int4 ch = g_chunks[ci];
    int start = ch.x, count = ch.y, k = ch.z;
    int ntap = 3 * k;

    for (int idx = threadIdx.x; idx < 33 * WROW; idx += blockDim.x) {
        int tap = idx >> 4;
        int q = (idx >> 1) & 7;
        float v = 0.0f;
        if (q < count && tap < ntap) {
            int i = g_sorted[start + q];
            int c = tap / k;
            int j = tap - c * k;
            v = weights[i * W_STRIDE + c * MAXK + j];
        }
        g_wT[ci * (33 * WROW) + idx] = v;
    }
    if (threadIdx.x < CHUNK) {
        float b = 0.0f;
        if (threadIdx.x < count) b = biases[g_sorted[start + threadIdx.x]];
        g_biasT[ci * CHUNK + threadIdx.x] = b;
    }
}

// ---------------------------------------------------------------------------
// Main conv kernel. f32x2 lanes pack adjacent t-points of the same kernel q.
// acc[rp][q]: t = warp*256 + lane*2 + 64*rp + {0,1}.
// Double-buffered chunk weights/bias/partials: ONE __syncthreads per chunk.
// ---------------------------------------------------------------------------
#define FMA2(a, x, w) asm("fma.rn.f32x2 %0, %1, %2, %0;" : "+l"(a) : "l"(x), "l"(w))

__device__ __forceinline__ void load_wrow(const float* __restrict__ wrow, ull w[8]) {
    ulonglong2 t;
    t = *(const ulonglong2*)(wrow + 0);  w[0] = t.x; w[1] = t.y;
    t = *(const ulonglong2*)(wrow + 4);  w[2] = t.x; w[3] = t.y;
    t = *(const ulonglong2*)(wrow + 8);  w[4] = t.x; w[5] = t.y;
    t = *(const ulonglong2*)(wrow + 12); w[6] = t.x; w[7] = t.y;
}

template <int K>
__device__ __forceinline__ void conv_vec(const float* __restrict__ sx,
                                         const float* __restrict__ sw,
                                         int d, int t0, ull acc[4][8]) {
    const int h = (K - 1) / 2;
    #pragma unroll
    for (int c = 0; c < 3; c++) {
        const float* xb = sx + c * XPITCH + PADL - h * d + t0;
        #pragma unroll
        for (int j = 0; j < K; j++) {
            ull w[8];
            load_wrow(sw + (c * K + j) * WROW, w);
            const float* xp = xb + j * d;
            ull xx[4];
            #pragma unroll
            for (int rp = 0; rp < 4; rp++)
                xx[rp] = *(const ull*)(xp + rp * 64);
            #pragma unroll
            for (int rp = 0; rp < 4; rp++) {
                #pragma unroll
                for (int q = 0; q < 8; q++) FMA2(acc[rp][q], xx[rp], w[q]);
            }
        }
    }
}

template <int K>
__device__ __forceinline__ void conv_d1(const float* __restrict__ sx,
                                        const float* __restrict__ sw,
                                        int t0, ull acc[4][8]) {
    const int h = (K - 1) / 2;
    #pragma unroll
    for (int c = 0; c < 3; c++) {
        const float* xb = sx + c * XPITCH + PADL - h + t0;
        #pragma unroll
        for (int j = 0; j < K; j++) {
            ull w[8];
            load_wrow(sw + (c * K + j) * WROW, w);
            const float* xp = xb + j;
            ull xx[4];
            if ((j - h) & 1) {
                #pragma unroll
                for (int rp = 0; rp < 4; rp++) {
                    float a = xp[rp * 64];
                    float b = xp[rp * 64 + 1];
                    asm("mov.b64 %0, {%1, %2};" : "=l"(xx[rp]) : "f"(a), "f"(b));
                }
            } else {
                #pragma unroll
                for (int rp = 0; rp < 4; rp++)
                    xx[rp] = *(const ull*)(xp + rp * 64);
            }
            #pragma unroll
            for (int rp = 0; rp < 4; rp++) {
                #pragma unroll
                for (int q = 0; q < 8; q++) FMA2(acc[rp][q], xx[rp], w[q]);
            }
        }
    }
}

__global__ void __launch_bounds__(128, 4)
rocket_main(const float* __restrict__ x, float* __restrict__ out) {
    __shared__ __align__(16) float sx[3 * XPITCH];
    __shared__ __align__(16) float sw[2][33 * WROW];
    __shared__ __align__(16) float sb[2][CHUNK];
    __shared__ float sred[2][4][CHUNK][2];

    const int nch = g_nchunks;
    const long long nit = (long long)nch * BATCH;
    const int nb = gridDim.x;
    long long s = (long long)blockIdx.x * nit / nb;
    long long e = (long long)(blockIdx.x + 1) * nit / nb;
    if (s >= e) return;

    int b  = (int)(s / nch);
    int ci = (int)(s - (long long)b * nch);

    const int warp = threadIdx.x >> 5;
    const int lane = threadIdx.x & 31;
    const int t0 = warp * 256 + lane * 2;

    // Prologue: zero halo once (never touched again), load x body, chunk 0 wts
    for (int idx = threadIdx.x; idx < 3 * XPITCH; idx += 128) sx[idx] = 0.0f;
    __syncthreads();
    for (int idx = threadIdx.x; idx < 3 * T_LEN; idx += 128) {
        int c = idx >> 10;
        int t = idx & (T_LEN - 1);
        sx[c * XPITCH + PADL + t] = x[b * 3 * T_LEN + idx];
    }
    for (int idx = threadIdx.x; idx < 33 * WROW; idx += 128)
        sw[0][idx] = g_wT[ci * (33 * WROW) + idx];
    if (threadIdx.x < CHUNK) sb[0][threadIdx.x] = g_biasT[ci * CHUNK + threadIdx.x];
    __syncthreads();

    int p = 0;
    for (long long it = s; it < e; it++) {
        int4 ch = g_chunks[ci];

        // init packed accumulators with {bias,bias}
        ull acc[4][8];
        {
            #pragma unroll
            for (int q = 0; q < 8; q++) {
                float bv = sb[p][q];
                ull bp2;
                asm("mov.b64 %0, {%1, %1};" : "=l"(bp2) : "f"(bv));
                #pragma unroll
                for (int rp = 0; rp < 4; rp++) acc[rp][q] = bp2;
            }
        }

        int d = ch.w;
        if (d == 1) {
            if (ch.z == 7)       conv_d1<7>(sx, sw[p], t0, acc);
            else if (ch.z == 9)  conv_d1<9>(sx, sw[p], t0, acc);
            else                 conv_d1<11>(sx, sw[p], t0, acc);
        } else {
            if (ch.z == 7)       conv_vec<7>(sx, sw[p], d, t0, acc);
            else if (ch.z == 9)  conv_vec<9>(sx, sw[p], d, t0, acc);
            else                 conv_vec<11>(sx, sw[p], d, t0, acc);
        }

        // prefetch next chunk's weights into the other buffer
        int nci = (ci + 1 == nch) ? 0 : ci + 1;
        if (it + 1 < e) {
            for (int idx = threadIdx.x; idx < 33 * WROW; idx += 128)
                sw[p ^ 1][idx] = g_wT[nci * (33 * WROW) + idx];
            if (threadIdx.x < CHUNK)
                sb[p ^ 1][threadIdx.x] = g_biasT[nci * CHUNK + threadIdx.x];
        }

        // epilogue: per kernel q, reduce 4 packed pairs -> warp butterfly
        #pragma unroll
        for (int q = 0; q < 8; q++) {
            float lo[4], hi[4];
            #pragma unroll
            for (int rp = 0; rp < 4; rp++)
                asm("mov.b64 {%0, %1}, %2;" : "=f"(lo[rp]), "=f"(hi[rp]) : "l"(acc[rp][q]));
            float m = fmaxf(fmaxf(fmaxf(lo[0], hi[0]), fmaxf(lo[1], hi[1])),
                            fmaxf(fmaxf(lo[2], hi[2]), fmaxf(lo[3], hi[3])));
            float c2 = 0.0f;
            #pragma unroll
            for (int rp = 0; rp < 4; rp++) {
                c2 += lo[rp] > 0.0f ? 1.0f : 0.0f;
                c2 += hi[rp] > 0.0f ? 1.0f : 0.0f;
            }
            #pragma unroll
            for (int o = 16; o > 0; o >>= 1) {
                m  = fmaxf(m, __shfl_xor_sync(0xffffffffu, m, o));
                c2 += __shfl_xor_sync(0xffffffffu, c2, o);
            }
            if (lane == 0) {
                sred[p][warp][q][0] = m;
                sred[p][warp][q][1] = c2;
            }
        }

        __syncthreads();  // the ONE steady-state barrier

        if (threadIdx.x < CHUNK) {
            int q = threadIdx.x;
            if (q < ch.y) {
                float m  = sred[p][0][q][0];
                float c2 = sred[p][0][q][1];
                #pragma unroll
                for (int w = 1; w < 4; w++) {
                    m = fmaxf(m, sred[p][w][q][0]);
                    c2 += sred[p][w][q][1];
                }
                int orig = g_sorted[ch.x + q];
                float2 o;
                o.x = m;
                o.y = c2 * (1.0f / 1024.0f);
                *(float2*)(out + (long long)b * OUT_STRIDE + 2 * orig) = o;
            }
        }

        // advance; reload x body on batch switch (halo stays zero)
        ci++;
        if (ci == nch) {
            ci = 0; b++;
            if (it + 1 < e) {
                for (int idx = threadIdx.x; idx < 3 * T_LEN; idx += 128) {
                    int c = idx >> 10;
                    int t = idx & (T_LEN - 1);
                    sx[c * XPITCH + PADL + t] = x[b * 3 * T_LEN + idx];
                }
                __syncthreads();
            }
        }
        p ^= 1;
    }
}

// ---------------------------------------------------------------------------
// Launch
// ---------------------------------------------------------------------------
extern "C" void kernel_launch(void* const* d_in, const int* in_sizes, int n_in,
                              void* d_out, int out_size) {
    const float* x       = (const float*)d_in[0];
    const float* weights = (const float*)d_in[1];
    const float* biases  = (const float*)d_in[2];
    float* out = (float*)d_out;

    rng_reset<<<1, 1>>>();
    rng_par<<<(N_KERNELS + 255) / 256, 256>>>();
    rng_seq<<<1, 1>>>();
    hist_kernel<<<(N_KERNELS + 127) / 128, 128>>>();
    offs_kernel<<<1, 32>>>();
    scatter_kernel<<<(N_KERNELS + 127) / 128, 128>>>();
    wt_kernel<<<MAXCHUNKS, 256>>>(weights, biases);

    int dev = 0, nsm = 148;
    cudaGetDevice(&dev);
    if (cudaDeviceGetAttribute(&nsm, cudaDevAttrMultiProcessorCount, dev) != cudaSuccess || nsm <= 0)
        nsm = 148;
    rocket_main<<<4 * nsm, 128>>>(x, out);
}

// round 7
// speedup vs baseline: 9.0846x; 2.5273x over previous
#include <cuda_runtime.h>
#include <cuda_bf16.h>
#include <stdint.h>

typedef unsigned long long ull;
typedef unsigned int uint;

// ---------------------------------------------------------------------------
// Problem constants
// ---------------------------------------------------------------------------
#define N_KERNELS 10000
#define IN_CH 3
#define T_LEN 1024
#define BATCH 64
#define MAXK 11
#define W_STRIDE (IN_CH * MAXK)     // 33
#define NGROUPS 15
#define CHUNK 32                    // kernels per chunk (2 m-tiles of 16)
#define MAXCH 352
#define OUT_STRIDE (2 * N_KERNELS)
#define PADL 80
#define XP (T_LEN + 2 * PADL)       // 1184
#define XSP (2 * IN_CH * XP)        // 7104 bf16 per batch (xh then xl)
#define NKMAX 7

__constant__ int c_dils[5] = {1, 2, 4, 8, 16};

// ---------------------------------------------------------------------------
// Device-global scratch
// ---------------------------------------------------------------------------
__device__ uint8_t g_kidx[N_KERNELS];
__device__ uint8_t g_didx[N_KERNELS];
__device__ uint8_t g_garr[N_KERNELS];
__device__ int     g_cnt[NGROUPS];
__device__ int     g_scnt[NGROUPS];
__device__ int     g_sorted[N_KERNELS];
__device__ int     g_nch;
__device__ int4    g_chunks[MAXCH];          // {start, count, k, dil}
__device__ int     g_rng_bad;
__device__ __align__(16) uint4 g_wfrag[MAXCH * 2 * NKMAX * 32]; // A fragments
__device__ float   g_biasT[MAXCH * CHUNK];
__device__ __align__(16) __nv_bfloat16 g_xsplit[BATCH * XSP];   // xh|xl images

// ---------------------------------------------------------------------------
// NumPy default_rng(0): SeedSequence -> PCG64 (XSL-RR) -> Lemire  (validated)
// ---------------------------------------------------------------------------
#define PCG_MH 2549297995355413924ull
#define PCG_ML 4865540595714422341ull

struct Pcg { ull shi, slo, ihi, ilo; int has32; uint buf; };

__device__ __forceinline__ void mul128(ull alo, ull ahi, ull blo, ull bhi,
                                       ull &rlo, ull &rhi) {
    rlo = alo * blo;
    rhi = __umul64hi(alo, blo) + alo * bhi + ahi * blo;
}
__device__ __forceinline__ void add128(ull &alo, ull &ahi, ull blo, ull bhi) {
    ull t = alo + blo;
    ahi = ahi + bhi + (t < alo ? 1ull : 0ull);
    alo = t;
}
__device__ __forceinline__ void pcg_step(Pcg &p) {
    ull nlo, nhi;
    mul128(p.slo, p.shi, PCG_ML, PCG_MH, nlo, nhi);
    add128(nlo, nhi, p.ilo, p.ihi);
    p.slo = nlo; p.shi = nhi;
}
__device__ __forceinline__ ull pcg_out(ull slo, ull shi) {
    uint rot = (uint)(shi >> 58);
    ull x = shi ^ slo;
    return (x >> rot) | (x << ((64u - rot) & 63u));
}
__device__ __forceinline__ uint pcg_next32(Pcg &p) {
    if (p.has32) { p.has32 = 0; return p.buf; }
    pcg_step(p);
    ull v = pcg_out(p.slo, p.shi);
    p.has32 = 1;
    p.buf = (uint)(v >> 32);
    return (uint)v;
}
__device__ __forceinline__ uint lemire32(Pcg &p, uint excl) {
    ull m = (ull)pcg_next32(p) * (ull)excl;
    uint leftover = (uint)m;
    if (leftover < excl) {
        uint thr = (uint)(0u - excl) % excl;
        while (leftover < thr) {
            m = (ull)pcg_next32(p) * (ull)excl;
            leftover = (uint)m;
        }
    }
    return (uint)(m >> 32);
}
__device__ __forceinline__ uint hashmix32(uint v, uint *hc) {
    v ^= *hc; *hc *= 0x931e8875u; v *= *hc; v ^= v >> 16; return v;
}
__device__ __forceinline__ uint mix32(uint x, uint y) {
    uint r = x * 0xca01f9ddu - y * 0x4973f715u;
    r ^= r >> 16; return r;
}
__device__ void pcg_seed0(Pcg &p) {
    uint pool[4];
    uint hc = 0x43b0d7e5u;
    for (int i = 0; i < 4; i++) pool[i] = hashmix32(0u, &hc);
    for (int s = 0; s < 4; s++)
        for (int d = 0; d < 4; d++)
            if (s != d) pool[d] = mix32(pool[d], hashmix32(pool[s], &hc));
    uint hb = 0x8b51f9ddu;
    uint w32[8];
    for (int i = 0; i < 8; i++) {
        uint v = pool[i & 3];
        v ^= hb; hb *= 0x58f38dedu; v *= hb; v ^= v >> 16;
        w32[i] = v;
    }
    ull s0 = (ull)w32[0] | ((ull)w32[1] << 32);
    ull s1 = (ull)w32[2] | ((ull)w32[3] << 32);
    ull s2 = (ull)w32[4] | ((ull)w32[5] << 32);
    ull s3 = (ull)w32[6] | ((ull)w32[7] << 32);
    p.shi = 0; p.slo = 0;
    p.ihi = (s2 << 1) | (s3 >> 63);
    p.ilo = (s3 << 1) | 1ull;
    p.has32 = 0; p.buf = 0;
    pcg_step(p);
    add128(p.slo, p.shi, s1, s0);
    pcg_step(p);
}

__global__ void rng_reset() {
    g_rng_bad = 0;
    for (int g = 0; g < NGROUPS; g++) g_cnt[g] = 0;
}

__global__ void rng_par() {
    int n = blockIdx.x * blockDim.x + threadIdx.x;
    if (n >= N_KERNELS) return;
    Pcg p;
    pcg_seed0(p);
    ull delta = (ull)(n + 1);
    ull am_lo = 1, am_hi = 0, ap_lo = 0, ap_hi = 0;
    ull cm_lo = PCG_ML, cm_hi = PCG_MH;
    ull cp_lo = p.ilo, cp_hi = p.ihi;
    while (delta) {
        if (delta & 1) {
            ull tlo, thi;
            mul128(am_lo, am_hi, cm_lo, cm_hi, tlo, thi);
            am_lo = tlo; am_hi = thi;
            mul128(ap_lo, ap_hi, cm_lo, cm_hi, tlo, thi);
            add128(tlo, thi, cp_lo, cp_hi);
            ap_lo = tlo; ap_hi = thi;
        }
        ull e_lo = cm_lo + 1;
        ull e_hi = cm_hi + (e_lo == 0 ? 1ull : 0ull);
        ull tlo, thi;
        mul128(e_lo, e_hi, cp_lo, cp_hi, tlo, thi);
        cp_lo = tlo; cp_hi = thi;
        mul128(cm_lo, cm_hi, cm_lo, cm_hi, tlo, thi);
        cm_lo = tlo; cm_hi = thi;
        delta >>= 1;
    }
    ull slo, shi;
    mul128(p.slo, p.shi, am_lo, am_hi, slo, shi);
    add128(slo, shi, ap_lo, ap_hi);
    ull out = pcg_out(slo, shi);
    uint lo = (uint)out;
    uint hi = (uint)(out >> 32);
    if (lo == 0u || hi == 0u) atomicOr(&g_rng_bad, 1);
    if (n < N_KERNELS / 2) {
        int j = 2 * n;
        g_kidx[j]     = (uint8_t)(((ull)lo * 3ull) >> 32);
        g_kidx[j + 1] = (uint8_t)(((ull)hi * 3ull) >> 32);
    } else {
        int j = 2 * n - N_KERNELS;
        g_didx[j]     = (uint8_t)(((ull)lo * 5ull) >> 32);
        g_didx[j + 1] = (uint8_t)(((ull)hi * 5ull) >> 32);
    }
}

__global__ void rng_seq() {
    if (threadIdx.x != 0 || blockIdx.x != 0) return;
    if (g_rng_bad == 0) return;
    Pcg p;
    pcg_seed0(p);
    for (int i = 0; i < N_KERNELS; i++) g_kidx[i] = (uint8_t)lemire32(p, 3u);
    for (int i = 0; i < N_KERNELS; i++) g_didx[i] = (uint8_t)lemire32(p, 5u);
}

// ---------------------------------------------------------------------------
// Grouping: histogram -> offsets/chunks -> scatter
// ---------------------------------------------------------------------------
__global__ void hist_kernel() {
    int i = blockIdx.x * blockDim.x + threadIdx.x;
    if (i >= N_KERNELS) return;
    int g = (int)g_kidx[i] * 5 + (int)g_didx[i];
    g_garr[i] = (uint8_t)g;
    atomicAdd(&g_cnt[g], 1);
}

__global__ void offs_kernel() {
    if (threadIdx.x != 0) return;
    int off = 0, nch = 0;
    for (int g = 0; g < NGROUPS; g++) {
        int ks  = 7 + 2 * (g / 5);
        int dil = c_dils[g % 5];
        int n   = g_cnt[g];
        g_scnt[g] = off;
        for (int s = 0; s < n; s += CHUNK) {
            int4 ch;
            ch.x = off + s;
            ch.y = (n - s < CHUNK) ? (n - s) : CHUNK;
            ch.z = ks;
            ch.w = dil;
            g_chunks[nch++] = ch;
        }
        off += n;
    }
    g_nch = nch;
}

__global__ void scatter_kernel() {
    int i = blockIdx.x * blockDim.x + threadIdx.x;
    if (i >= N_KERNELS) return;
    int p = atomicAdd(&g_scnt[g_garr[i]], 1);
    g_sorted[p] = i;
}

// ---------------------------------------------------------------------------
// A-fragment image: fragment-order bf16 weights for mma.sync m16n8k16.
// K layout (term-major): kk = s*ntap + c*k + j, s in {0:wh,1:wl,2:wh}.
// frag uint4 per lane: x={(g,2t),(g,2t+1)}, y={(g+8,2t),(g+8,2t+1)},
//                      z={(g,2t+8),(g,2t+9)}, w={(g+8,2t+8),(g+8,2t+9)}
// ---------------------------------------------------------------------------
__device__ __forceinline__ unsigned short welem(const float* __restrict__ weights,
                                                const int* __restrict__ sorted,
                                                int start, int count, int k,
                                                int ntap, int row, int kk) {
    float v = 0.0f;
    bool lo = false;
    if (row < count && kk < 3 * ntap) {
        int s  = kk / ntap;
        int rr = kk - s * ntap;
        int c  = rr / k;
        int j  = rr - c * k;
        v = weights[sorted[start + row] * W_STRIDE + c * MAXK + j];
        lo = (s == 1);
    }
    __nv_bfloat16 vh = __float2bfloat16(v);
    __nv_bfloat16 o = lo ? __float2bfloat16(v - __bfloat162float(vh)) : vh;
    unsigned short u;
    memcpy(&u, &o, 2);
    return u;
}

__global__ void wimg_kernel(const float* __restrict__ weights,
                            const float* __restrict__ biases) {
    int ci = blockIdx.x;
    if (ci >= g_nch) return;
    int4 ch = g_chunks[ci];
    int start = ch.x, count = ch.y, k = ch.z;
    int ntap = 3 * k;

    for (int idx = threadIdx.x; idx < 2 * NKMAX * 32; idx += blockDim.x) {
        int mt   = idx / (NKMAX * 32);
        int rem  = idx - mt * (NKMAX * 32);
        int kc   = rem / 32;
        int lane = rem & 31;
        int g = lane >> 2;
        int t = lane & 3;
        int r0 = mt * 16 + g;
        int r1 = r0 + 8;
        int k0 = kc * 16 + 2 * t;
        uint4 f;
        f.x = (uint)welem(weights, g_sorted, start, count, k, ntap, r0, k0)
            | ((uint)welem(weights, g_sorted, start, count, k, ntap, r0, k0 + 1) << 16);
        f.y = (uint)welem(weights, g_sorted, start, count, k, ntap, r1, k0)
            | ((uint)welem(weights, g_sorted, start, count, k, ntap, r1, k0 + 1) << 16);
        f.z = (uint)welem(weights, g_sorted, start, count, k, ntap, r0, k0 + 8)
            | ((uint)welem(weights, g_sorted, start, count, k, ntap, r0, k0 + 9) << 16);
        f.w = (uint)welem(weights, g_sorted, start, count, k, ntap, r1, k0 + 8)
            | ((uint)welem(weights, g_sorted, start, count, k, ntap, r1, k0 + 9) << 16);
        g_wfrag[(ci * 2 + mt) * (NKMAX * 32) + kc * 32 + lane] = f;
    }
    if (threadIdx.x < CHUNK) {
        float b = 0.0f;
        if (threadIdx.x < count) b = biases[g_sorted[start + threadIdx.x]];
        g_biasT[ci * CHUNK + threadIdx.x] = b;
    }
}

// ---------------------------------------------------------------------------
// x split image per batch: [arr(2: xh,xl)][c(3)][XP] bf16, halo zeros
// ---------------------------------------------------------------------------
__global__ void xsplit_kernel(const float* __restrict__ x) {
    int b = blockIdx.x;
    __nv_bfloat16* dst = g_xsplit + b * XSP;
    for (int i = threadIdx.x; i < XSP; i += blockDim.x) {
        int arr = i / (IN_CH * XP);
        int r   = i - arr * (IN_CH * XP);
        int c   = r / XP;
        int p   = r - c * XP;
        int t   = p - PADL;
        float v = (t >= 0 && t < T_LEN) ? x[b * IN_CH * T_LEN + c * T_LEN + t] : 0.0f;
        __nv_bfloat16 vh = __float2bfloat16(v);
        dst[i] = arr ? __float2bfloat16(v - __bfloat162float(vh)) : vh;
    }
}

// ---------------------------------------------------------------------------
// Main HMMA kernel
// ---------------------------------------------------------------------------
__device__ __forceinline__ void mma16816(float c[4], uint4 a, uint b0, uint b1) {
    asm("mma.sync.aligned.m16n8k16.row.col.f32.bf16.bf16.f32 "
        "{%0,%1,%2,%3}, {%4,%5,%6,%7}, {%8,%9}, {%0,%1,%2,%3};"
        : "+f"(c[0]), "+f"(c[1]), "+f"(c[2]), "+f"(c[3])
        : "r"(a.x), "r"(a.y), "r"(a.z), "r"(a.w), "r"(b0), "r"(b1));
}

__device__ __forceinline__ uint smem_u32(const void* p) {
    uint a;
    asm("{ .reg .u64 tmp; cvta.to.shared.u64 tmp, %1; cvt.u32.u64 %0, tmp; }"
        : "=r"(a) : "l"(p));
    return a;
}

__device__ __forceinline__ uint lds_pair(uint a0, uint a1) {
    unsigned short u0, u1;
    asm("ld.shared.u16 %0, [%1];" : "=h"(u0) : "r"(a0));
    asm("ld.shared.u16 %0, [%1];" : "=h"(u1) : "r"(a1));
    return (uint)u0 | ((uint)u1 << 16);
}

template <int K, int NK>
__global__ void __launch_bounds__(128)
rocket_mma(float* __restrict__ out) {
    int ci = blockIdx.x;
    if (ci >= g_nch) return;
    int4 ch = g_chunks[ci];
    if (ch.z != K) return;
    int b = blockIdx.y;
    const int dil = ch.w;
    const int ntap = 3 * K;
    const int h = (K - 1) / 2;

    __shared__ __align__(16) __nv_bfloat16 xs[XSP];
    __shared__ __align__(16) uint soff[NKMAX][4][4];
    __shared__ float sred[4][CHUNK][2];

    const int tid = threadIdx.x;
    const int warp = tid >> 5;
    const int lane = tid & 31;
    const int g = lane >> 2;
    const int t = lane & 3;

    // copy x split image for this batch (888 uint4)
    {
        const uint4* src = (const uint4*)(g_xsplit + b * XSP);
        uint4* dst = (uint4*)xs;
        #pragma unroll
        for (int i = 0; i < 7; i++) {
            int p = tid + 128 * i;
            if (p < XSP / 8) dst[p] = src[p];
        }
    }

    // build B-offset address table
    uint xsbase = smem_u32(xs);
    if (tid < NK * 16) {
        int kc = tid >> 4;
        int lg = (tid >> 2) & 3;
        int e  = tid & 3;
        int kk = kc * 16 + 2 * lg + (e & 1) + ((e & 2) << 2);
        uint addr = xsbase;
        if (kk < ntap * 3) {
            int s  = kk / ntap;
            int rr = kk - s * ntap;
            int c  = rr / K;
            int j  = rr - c * K;
            int arr = (s == 2) ? 1 : 0;
            addr = xsbase + (uint)(((arr * 3 + c) * XP + PADL + (j - h) * dil) * 2);
        }
        soff[kc][lg][e] = addr;
    }

    // load A fragments (held in registers for the whole block)
    uint4 afr[2][NK];
    {
        const uint4* wf = g_wfrag + (ci * 2) * (NKMAX * 32);
        #pragma unroll
        for (int mt = 0; mt < 2; mt++)
            #pragma unroll
            for (int kc = 0; kc < NK; kc++)
                afr[mt][kc] = wf[mt * (NKMAX * 32) + kc * 32 + lane];
    }

    // negated biases for this thread's 4 C rows: {g, g+8, 16+g, 24+g}
    float nb[4];
    nb[0] = -g_biasT[ci * CHUNK + g];
    nb[1] = -g_biasT[ci * CHUNK + g + 8];
    nb[2] = -g_biasT[ci * CHUNK + 16 + g];
    nb[3] = -g_biasT[ci * CHUNK + 24 + g];

    __syncthreads();

    float mx[4] = {-3.4e38f, -3.4e38f, -3.4e38f, -3.4e38f};
    float ct[4] = {0.0f, 0.0f, 0.0f, 0.0f};

    uint colb = (uint)(warp * 512 + g * 2);   // byte offset of this thread's col

    #pragma unroll 1
    for (int nt = 0; nt < 32; nt++) {
        float C0[4] = {0, 0, 0, 0};
        float C1[4] = {0, 0, 0, 0};
        #pragma unroll
        for (int kc = 0; kc < NK; kc++) {
            uint4 of = *(const uint4*)&soff[kc][t][0];
            uint b0 = lds_pair(of.x + colb, of.y + colb);
            uint b1 = lds_pair(of.z + colb, of.w + colb);
            mma16816(C0, afr[0][kc], b0, b1);
            mma16816(C1, afr[1][kc], b0, b1);
        }
        mx[0] = fmaxf(mx[0], fmaxf(C0[0], C0[1]));
        mx[1] = fmaxf(mx[1], fmaxf(C0[2], C0[3]));
        mx[2] = fmaxf(mx[2], fmaxf(C1[0], C1[1]));
        mx[3] = fmaxf(mx[3], fmaxf(C1[2], C1[3]));
        ct[0] += (C0[0] > nb[0] ? 1.0f : 0.0f) + (C0[1] > nb[0] ? 1.0f : 0.0f);
        ct[1] += (C0[2] > nb[1] ? 1.0f : 0.0f) + (C0[3] > nb[1] ? 1.0f : 0.0f);
        ct[2] += (C1[0] > nb[2] ? 1.0f : 0.0f) + (C1[1] > nb[2] ? 1.0f : 0.0f);
        ct[3] += (C1[2] > nb[3] ? 1.0f : 0.0f) + (C1[3] > nb[3] ? 1.0f : 0.0f);
        colb += 16;
    }

    // reduce across the 4 threads sharing each row (t = lane&3)
    #pragma unroll
    for (int o = 1; o <= 2; o <<= 1) {
        #pragma unroll
        for (int i = 0; i < 4; i++) {
            mx[i] = fmaxf(mx[i], __shfl_xor_sync(0xffffffffu, mx[i], o));
            ct[i] += __shfl_xor_sync(0xffffffffu, ct[i], o);
        }
    }
    if (t == 0) {
        sred[warp][g][0]      = mx[0];  sred[warp][g][1]      = ct[0];
        sred[warp][g + 8][0]  = mx[1];  sred[warp][g + 8][1]  = ct[1];
        sred[warp][g + 16][0] = mx[2];  sred[warp][g + 16][1] = ct[2];
        sred[warp][g + 24][0] = mx[3];  sred[warp][g + 24][1] = ct[3];
    }
    __syncthreads();

    if (tid < CHUNK && tid < ch.y) {
        float m  = sred[0][tid][0];
        float c2 = sred[0][tid][1];
        #pragma unroll
        for (int w = 1; w < 4; w++) {
            m = fmaxf(m, sred[w][tid][0]);
            c2 += sred[w][tid][1];
        }
        int orig = g_sorted[ch.x + tid];
        float bias = g_biasT[ci * CHUNK + tid];
        float2 o;
        o.x = m + bias;
        o.y = c2 * (1.0f / 1024.0f);
        *(float2*)(out + (size_t)b * OUT_STRIDE + 2 * orig) = o;
    }
}

// ---------------------------------------------------------------------------
// Launch
// ---------------------------------------------------------------------------
extern "C" void kernel_launch(void* const* d_in, const int* in_sizes, int n_in,
                              void* d_out, int out_size) {
    const float* x       = (const float*)d_in[0];
    const float* weights = (const float*)d_in[1];
    const float* biases  = (const float*)d_in[2];
    float* out = (float*)d_out;

    rng_reset<<<1, 1>>>();
    rng_par<<<(N_KERNELS + 255) / 256, 256>>>();
    rng_seq<<<1, 1>>>();
    hist_kernel<<<(N_KERNELS + 127) / 128, 128>>>();
    offs_kernel<<<1, 32>>>();
    scatter_kernel<<<(N_KERNELS + 127) / 128, 128>>>();
    wimg_kernel<<<MAXCH, 128>>>(weights, biases);
    xsplit_kernel<<<BATCH, 128>>>(x);

    dim3 grid(MAXCH, BATCH);
    rocket_mma<7, 4><<<grid, 128>>>(out);
    rocket_mma<9, 6><<<grid, 128>>>(out);
    rocket_mma<11, 7><<<grid, 128>>>(out);
}

// round 8
// speedup vs baseline: 15.4755x; 1.7035x over previous
#include <cuda_runtime.h>
#include <cuda_fp16.h>
#include <stdint.h>

typedef unsigned long long ull;
typedef unsigned int uint;

// ---------------------------------------------------------------------------
// Problem constants
// ---------------------------------------------------------------------------
#define N_KERNELS 10000
#define IN_CH 3
#define T_LEN 1024
#define BATCH 64
#define MAXK 11
#define W_STRIDE (IN_CH * MAXK)     // 33
#define NGROUPS 15
#define CHUNK 32                    // kernels per chunk (2 m-tiles of 16)
#define MAXCH 352
#define OUT_STRIDE (2 * N_KERNELS)
#define PADL 80
#define XP (T_LEN + 2 * PADL)       // 1184 elements
#define XDUP (IN_CH * XP)           // 3552 u32 per batch (dup fp16 pairs)
#define NKMAX 5                     // k16 chunks: k=7:3, k=9:4, k=11:5

__constant__ int c_dils[5] = {1, 2, 4, 8, 16};

// ---------------------------------------------------------------------------
// Device-global scratch
// ---------------------------------------------------------------------------
__device__ uint8_t g_kidx[N_KERNELS];
__device__ uint8_t g_didx[N_KERNELS];
__device__ uint8_t g_garr[N_KERNELS];
__device__ int     g_cnt[NGROUPS];
__device__ int     g_scnt[NGROUPS];
__device__ int     g_sorted[N_KERNELS];
__device__ int     g_nch;
__device__ int4    g_chunks[MAXCH];          // {start, count, k, dil}
__device__ int     g_rng_bad;
__device__ __align__(16) uint4 g_wfrag[MAXCH * 2 * NKMAX * 32]; // A frags (wh,wl pairs)
__device__ float   g_biasT[MAXCH * CHUNK];
__device__ __align__(16) uint g_xdup[BATCH * XDUP];             // {xh,xh} u32 images

// ---------------------------------------------------------------------------
// NumPy default_rng(0): SeedSequence -> PCG64 (XSL-RR) -> Lemire  (validated)
// ---------------------------------------------------------------------------
#define PCG_MH 2549297995355413924ull
#define PCG_ML 4865540595714422341ull

struct Pcg { ull shi, slo, ihi, ilo; int has32; uint buf; };

__device__ __forceinline__ void mul128(ull alo, ull ahi, ull blo, ull bhi,
                                       ull &rlo, ull &rhi) {
    rlo = alo * blo;
    rhi = __umul64hi(alo, blo) + alo * bhi + ahi * blo;
}
__device__ __forceinline__ void add128(ull &alo, ull &ahi, ull blo, ull bhi) {
    ull t = alo + blo;
    ahi = ahi + bhi + (t < alo ? 1ull : 0ull);
    alo = t;
}
__device__ __forceinline__ void pcg_step(Pcg &p) {
    ull nlo, nhi;
    mul128(p.slo, p.shi, PCG_ML, PCG_MH, nlo, nhi);
    add128(nlo, nhi, p.ilo, p.ihi);
    p.slo = nlo; p.shi = nhi;
}
__device__ __forceinline__ ull pcg_out(ull slo, ull shi) {
    uint rot = (uint)(shi >> 58);
    ull x = shi ^ slo;
    return (x >> rot) | (x << ((64u - rot) & 63u));
}
__device__ __forceinline__ uint pcg_next32(Pcg &p) {
    if (p.has32) { p.has32 = 0; return p.buf; }
    pcg_step(p);
    ull v = pcg_out(p.slo, p.shi);
    p.has32 = 1;
    p.buf = (uint)(v >> 32);
    return (uint)v;
}
__device__ __forceinline__ uint lemire32(Pcg &p, uint excl) {
    ull m = (ull)pcg_next32(p) * (ull)excl;
    uint leftover = (uint)m;
    if (leftover < excl) {
        uint thr = (uint)(0u - excl) % excl;
        while (leftover < thr) {
            m = (ull)pcg_next32(p) * (ull)excl;
            leftover = (uint)m;
        }
    }
    return (uint)(m >> 32);
}
__device__ __forceinline__ uint hashmix32(uint v, uint *hc) {
    v ^= *hc; *hc *= 0x931e8875u; v *= *hc; v ^= v >> 16; return v;
}
__device__ __forceinline__ uint mix32(uint x, uint y) {
    uint r = x * 0xca01f9ddu - y * 0x4973f715u;
    r ^= r >> 16; return r;
}
__device__ void pcg_seed0(Pcg &p) {
    uint pool[4];
    uint hc = 0x43b0d7e5u;
    for (int i = 0; i < 4; i++) pool[i] = hashmix32(0u, &hc);
    for (int s = 0; s < 4; s++)
        for (int d = 0; d < 4; d++)
            if (s != d) pool[d] = mix32(pool[d], hashmix32(pool[s], &hc));
    uint hb = 0x8b51f9ddu;
    uint w32[8];
    for (int i = 0; i < 8; i++) {
        uint v = pool[i & 3];
        v ^= hb; hb *= 0x58f38dedu; v *= hb; v ^= v >> 16;
        w32[i] = v;
    }
    ull s0 = (ull)w32[0] | ((ull)w32[1] << 32);
    ull s1 = (ull)w32[2] | ((ull)w32[3] << 32);
    ull s2 = (ull)w32[4] | ((ull)w32[5] << 32);
    ull s3 = (ull)w32[6] | ((ull)w32[7] << 32);
    p.shi = 0; p.slo = 0;
    p.ihi = (s2 << 1) | (s3 >> 63);
    p.ilo = (s3 << 1) | 1ull;
    p.has32 = 0; p.buf = 0;
    pcg_step(p);
    add128(p.slo, p.shi, s1, s0);
    pcg_step(p);
}

__global__ void rng_reset() {
    g_rng_bad = 0;
    for (int g = 0; g < NGROUPS; g++) g_cnt[g] = 0;
}

__global__ void rng_par() {
    int n = blockIdx.x * blockDim.x + threadIdx.x;
    if (n >= N_KERNELS) return;
    Pcg p;
    pcg_seed0(p);
    ull delta = (ull)(n + 1);
    ull am_lo = 1, am_hi = 0, ap_lo = 0, ap_hi = 0;
    ull cm_lo = PCG_ML, cm_hi = PCG_MH;
    ull cp_lo = p.ilo, cp_hi = p.ihi;
    while (delta) {
        if (delta & 1) {
            ull tlo, thi;
            mul128(am_lo, am_hi, cm_lo, cm_hi, tlo, thi);
            am_lo = tlo; am_hi = thi;
            mul128(ap_lo, ap_hi, cm_lo, cm_hi, tlo, thi);
            add128(tlo, thi, cp_lo, cp_hi);
            ap_lo = tlo; ap_hi = thi;
        }
        ull e_lo = cm_lo + 1;
        ull e_hi = cm_hi + (e_lo == 0 ? 1ull : 0ull);
        ull tlo, thi;
        mul128(e_lo, e_hi, cp_lo, cp_hi, tlo, thi);
        cp_lo = tlo; cp_hi = thi;
        mul128(cm_lo, cm_hi, cm_lo, cm_hi, tlo, thi);
        cm_lo = tlo; cm_hi = thi;
        delta >>= 1;
    }
    ull slo, shi;
    mul128(p.slo, p.shi, am_lo, am_hi, slo, shi);
    add128(slo, shi, ap_lo, ap_hi);
    ull out = pcg_out(slo, shi);
    uint lo = (uint)out;
    uint hi = (uint)(out >> 32);
    if (lo == 0u || hi == 0u) atomicOr(&g_rng_bad, 1);
    if (n < N_KERNELS / 2) {
        int j = 2 * n;
        g_kidx[j]     = (uint8_t)(((ull)lo * 3ull) >> 32);
        g_kidx[j + 1] = (uint8_t)(((ull)hi * 3ull) >> 32);
    } else {
        int j = 2 * n - N_KERNELS;
        g_didx[j]     = (uint8_t)(((ull)lo * 5ull) >> 32);
        g_didx[j + 1] = (uint8_t)(((ull)hi * 5ull) >> 32);
    }
}

__global__ void rng_seq() {
    if (threadIdx.x != 0 || blockIdx.x != 0) return;
    if (g_rng_bad == 0) return;
    Pcg p;
    pcg_seed0(p);
    for (int i = 0; i < N_KERNELS; i++) g_kidx[i] = (uint8_t)lemire32(p, 3u);
    for (int i = 0; i < N_KERNELS; i++) g_didx[i] = (uint8_t)lemire32(p, 5u);
}

// ---------------------------------------------------------------------------
// Grouping: histogram -> offsets/chunks -> scatter
// ---------------------------------------------------------------------------
__global__ void hist_kernel() {
    int i = blockIdx.x * blockDim.x + threadIdx.x;
    if (i >= N_KERNELS) return;
    int g = (int)g_kidx[i] * 5 + (int)g_didx[i];
    g_garr[i] = (uint8_t)g;
    atomicAdd(&g_cnt[g], 1);
}

__global__ void offs_kernel() {
    if (threadIdx.x != 0) return;
    int off = 0, nch = 0;
    for (int g = 0; g < NGROUPS; g++) {
        int ks  = 7 + 2 * (g / 5);
        int dil = c_dils[g % 5];
        int n   = g_cnt[g];
        g_scnt[g] = off;
        for (int s = 0; s < n; s += CHUNK) {
            int4 ch;
            ch.x = off + s;
            ch.y = (n - s < CHUNK) ? (n - s) : CHUNK;
            ch.z = ks;
            ch.w = dil;
            g_chunks[nch++] = ch;
        }
        off += n;
    }
    g_nch = nch;
}

__global__ void scatter_kernel() {
    int i = blockIdx.x * blockDim.x + threadIdx.x;
    if (i >= N_KERNELS) return;
    int p = atomicAdd(&g_scnt[g_garr[i]], 1);
    g_sorted[p] = i;
}

// ---------------------------------------------------------------------------
// A-fragment image: fp16 (wh, wl) pairs in mma.m16n8k16 fragment order.
// K slot 2p = wh of tap-pair p, slot 2p+1 = wl. Pair p -> (c = p/k, j = p%k),
// zero for p >= 3k. Fragment uint4 per lane (g=lane>>2, t=lane&3):
//   x={(r0,2t),(r0,2t+1)}, y={(r0+8,..)}, z={(r0,2t+8),(r0,2t+9)}, w={(r0+8,..)}
// ---------------------------------------------------------------------------
__device__ __forceinline__ unsigned short whalf(const float* __restrict__ weights,
                                                const int* __restrict__ sorted,
                                                int start, int count, int k,
                                                int row, int slot) {
    int p = slot >> 1;
    float v = 0.0f;
    if (row < count && p < 3 * k) {
        int c = p / k;
        int j = p - c * k;
        v = weights[sorted[start + row] * W_STRIDE + c * MAXK + j];
    }
    __half vh = __float2half(v);
    __half o = (slot & 1) ? __float2half(v - __half2float(vh)) : vh;
    unsigned short u;
    memcpy(&u, &o, 2);
    return u;
}

__global__ void wimg_kernel(const float* __restrict__ weights,
                            const float* __restrict__ biases) {
    int ci = blockIdx.x;
    if (ci >= g_nch) return;
    int4 ch = g_chunks[ci];
    int start = ch.x, count = ch.y, k = ch.z;

    for (int idx = threadIdx.x; idx < 2 * NKMAX * 32; idx += blockDim.x) {
        int mt   = idx / (NKMAX * 32);
        int rem  = idx - mt * (NKMAX * 32);
        int kc   = rem / 32;
        int lane = rem & 31;
        int g = lane >> 2;
        int t = lane & 3;
        int r0 = mt * 16 + g;
        int r1 = r0 + 8;
        int k0 = kc * 16 + 2 * t;
        uint4 f;
        f.x = (uint)whalf(weights, g_sorted, start, count, k, r0, k0)
            | ((uint)whalf(weights, g_sorted, start, count, k, r0, k0 + 1) << 16);
        f.y = (uint)whalf(weights, g_sorted, start, count, k, r1, k0)
            | ((uint)whalf(weights, g_sorted, start, count, k, r1, k0 + 1) << 16);
        f.z = (uint)whalf(weights, g_sorted, start, count, k, r0, k0 + 8)
            | ((uint)whalf(weights, g_sorted, start, count, k, r0, k0 + 9) << 16);
        f.w = (uint)whalf(weights, g_sorted, start, count, k, r1, k0 + 8)
            | ((uint)whalf(weights, g_sorted, start, count, k, r1, k0 + 9) << 16);
        g_wfrag[(ci * 2 + mt) * (NKMAX * 32) + kc * 32 + lane] = f;
    }
    if (threadIdx.x < CHUNK) {
        float b = 0.0f;
        if (threadIdx.x < count) b = biases[g_sorted[start + threadIdx.x]];
        g_biasT[ci * CHUNK + threadIdx.x] = b;
    }
}

// ---------------------------------------------------------------------------
// x dup image per batch: u32 {xh, xh} with PADL halo zeros
// ---------------------------------------------------------------------------
__global__ void xdup_kernel(const float* __restrict__ x) {
    int b = blockIdx.x;
    uint* dst = g_xdup + b * XDUP;
    for (int i = threadIdx.x; i < XDUP; i += blockDim.x) {
        int c = i / XP;
        int p = i - c * XP;
        int t = p - PADL;
        float v = (t >= 0 && t < T_LEN) ? x[b * IN_CH * T_LEN + c * T_LEN + t] : 0.0f;
        __half h = __float2half(v);
        unsigned short u;
        memcpy(&u, &h, 2);
        dst[i] = (uint)u * 0x00010001u;
    }
}

// ---------------------------------------------------------------------------
// Main HMMA kernel (merged; runtime k dispatch into templated paths)
// ---------------------------------------------------------------------------
__device__ __forceinline__ void mma16816h(float c[4], uint4 a, uint b0, uint b1) {
    asm("mma.sync.aligned.m16n8k16.row.col.f32.f16.f16.f32 "
        "{%0,%1,%2,%3}, {%4,%5,%6,%7}, {%8,%9}, {%0,%1,%2,%3};"
        : "+f"(c[0]), "+f"(c[1]), "+f"(c[2]), "+f"(c[3])
        : "r"(a.x), "r"(a.y), "r"(a.z), "r"(a.w), "r"(b0), "r"(b1));
}

template <int K>
__device__ __forceinline__ int pidx(int P, int dil) {
    const int h = (K - 1) / 2;
    if (P >= 3 * K) return 0;
    int c = P / K;          // compile-time K -> mul-shift
    int j = P - c * K;
    return c * XP + PADL + (j - h) * dil;
}

template <int K, int NK>
__device__ __forceinline__ void run_mma(int4 ch, int b, int ci,
                                        const uint* __restrict__ xs,
                                        float (*sredm)[CHUNK], int (*sredc)[CHUNK],
                                        float* __restrict__ out) {
    const int tid  = threadIdx.x;
    const int warp = tid >> 5;
    const int lane = tid & 31;
    const int g = lane >> 2;
    const int t = lane & 3;
    const int dil = ch.w;
    const int wg = warp * 256 + g;

    // B base indices (u32 elements) for this lane's pairs, per kc
    uint ix0[NK], ix1[NK];
    #pragma unroll
    for (int kc = 0; kc < NK; kc++) {
        ix0[kc] = (uint)(pidx<K>(kc * 8 + t, dil) + wg);
        ix1[kc] = (uint)(pidx<K>(kc * 8 + 4 + t, dil) + wg);
    }

    // A fragments (registers for the whole block)
    uint4 a0[NK], a1[NK];
    {
        const uint4* wf = g_wfrag + (ci * 2) * (NKMAX * 32);
        #pragma unroll
        for (int kc = 0; kc < NK; kc++) {
            a0[kc] = wf[kc * 32 + lane];
            a1[kc] = wf[NKMAX * 32 + kc * 32 + lane];
        }
    }

    // negated biases for this thread's 4 C rows
    float nb[4];
    nb[0] = -g_biasT[ci * CHUNK + g];
    nb[1] = -g_biasT[ci * CHUNK + g + 8];
    nb[2] = -g_biasT[ci * CHUNK + 16 + g];
    nb[3] = -g_biasT[ci * CHUNK + 24 + g];

    float mx[4] = {-3.4e38f, -3.4e38f, -3.4e38f, -3.4e38f};
    int ct[4] = {0, 0, 0, 0};

    #pragma unroll 8
    for (int nt = 0; nt < 32; nt++) {
        float C0[4] = {0, 0, 0, 0};
        float C1[4] = {0, 0, 0, 0};
        #pragma unroll
        for (int kc = 0; kc < NK; kc++) {
            uint b0 = xs[ix0[kc] + nt * 8];
            uint b1 = xs[ix1[kc] + nt * 8];
            mma16816h(C0, a0[kc], b0, b1);
            mma16816h(C1, a1[kc], b0, b1);
        }
        mx[0] = fmaxf(mx[0], fmaxf(C0[0], C0[1]));
        mx[1] = fmaxf(mx[1], fmaxf(C0[2], C0[3]));
        mx[2] = fmaxf(mx[2], fmaxf(C1[0], C1[1]));
        mx[3] = fmaxf(mx[3], fmaxf(C1[2], C1[3]));
        if (C0[0] > nb[0]) ct[0]++;
        if (C0[1] > nb[0]) ct[0]++;
        if (C0[2] > nb[1]) ct[1]++;
        if (C0[3] > nb[1]) ct[1]++;
        if (C1[0] > nb[2]) ct[2]++;
        if (C1[1] > nb[2]) ct[2]++;
        if (C1[2] > nb[3]) ct[3]++;
        if (C1[3] > nb[3]) ct[3]++;
    }

    // reduce across the 4 threads sharing each row
    #pragma unroll
    for (int o = 1; o <= 2; o <<= 1) {
        #pragma unroll
        for (int i = 0; i < 4; i++) {
            mx[i] = fmaxf(mx[i], __shfl_xor_sync(0xffffffffu, mx[i], o));
            ct[i] += __shfl_xor_sync(0xffffffffu, ct[i], o);
        }
    }
    if (t == 0) {
        sredm[warp][g]      = mx[0];  sredc[warp][g]      = ct[0];
        sredm[warp][g + 8]  = mx[1];  sredc[warp][g + 8]  = ct[1];
        sredm[warp][g + 16] = mx[2];  sredc[warp][g + 16] = ct[2];
        sredm[warp][g + 24] = mx[3];  sredc[warp][g + 24] = ct[3];
    }
    __syncthreads();

    if (tid < CHUNK && tid < ch.y) {
        float m = sredm[0][tid];
        int c2 = sredc[0][tid];
        #pragma unroll
        for (int w = 1; w < 4; w++) {
            m = fmaxf(m, sredm[w][tid]);
            c2 += sredc[w][tid];
        }
        int orig = g_sorted[ch.x + tid];
        float bias = g_biasT[ci * CHUNK + tid];
        float2 o;
        o.x = m + bias;
        o.y = (float)c2 * (1.0f / 1024.0f);
        *(float2*)(out + (size_t)b * OUT_STRIDE + 2 * orig) = o;
    }
}

__global__ void __launch_bounds__(128)
rocket_mma(float* __restrict__ out) {
    int ci = blockIdx.x;
    if (ci >= g_nch) return;
    int4 ch = g_chunks[ci];
    int b = blockIdx.y;

    __shared__ __align__(16) uint xs[XDUP];
    __shared__ float sredm[4][CHUNK];
    __shared__ int   sredc[4][CHUNK];

    // copy this batch's dup image (888 uint4)
    {
        const uint4* src = (const uint4*)(g_xdup + b * XDUP);
        uint4* dst = (uint4*)xs;
        #pragma unroll
        for (int i = 0; i < 7; i++) {
            int p = threadIdx.x + 128 * i;
            if (p < XDUP / 4) dst[p] = src[p];
        }
    }
    __syncthreads();

    if (ch.z == 7)      run_mma<7, 3>(ch, b, ci, xs, sredm, sredc, out);
    else if (ch.z == 9) run_mma<9, 4>(ch, b, ci, xs, sredm, sredc, out);
    else                run_mma<11, 5>(ch, b, ci, xs, sredm, sredc, out);
}

// ---------------------------------------------------------------------------
// Launch
// ---------------------------------------------------------------------------
extern "C" void kernel_launch(void* const* d_in, const int* in_sizes, int n_in,
                              void* d_out, int out_size) {
    const float* x       = (const float*)d_in[0];
    const float* weights = (const float*)d_in[1];
    const float* biases  = (const float*)d_in[2];
    float* out = (float*)d_out;

    rng_reset<<<1, 1>>>();
    rng_par<<<(N_KERNELS + 255) / 256, 256>>>();
    rng_seq<<<1, 1>>>();
    hist_kernel<<<(N_KERNELS + 127) / 128, 128>>>();
    offs_kernel<<<1, 32>>>();
    scatter_kernel<<<(N_KERNELS + 127) / 128, 128>>>();
    wimg_kernel<<<MAXCH, 128>>>(weights, biases);
    xdup_kernel<<<BATCH, 128>>>(x);

    rocket_mma<<<dim3(MAXCH, BATCH), 128>>>(out);
}

// round 10
// speedup vs baseline: 21.4266x; 1.3845x over previous
#include <cuda_runtime.h>
#include <cuda_fp16.h>
#include <stdint.h>

typedef unsigned long long ull;
typedef unsigned int uint;

// ---------------------------------------------------------------------------
// Problem constants
// ---------------------------------------------------------------------------
#define N_KERNELS 10000
#define IN_CH 3
#define T_LEN 1024
#define BATCH 64
#define MAXK 11
#define W_STRIDE (IN_CH * MAXK)     // 33
#define NGROUPS 15
#define NDIL 5
#define CHUNK 32                    // kernels per chunk (2 m-tiles of 16)
#define MAXCH 352
#define OUT_STRIDE (2 * N_KERNELS)
#define PADL 80
#define XPE 1216                    // PADL + 1024 + 96 (max right reach) + pad
#define XPAIR (IN_CH * XPE)         // 3648 u32 per (batch, dil)
#define NKMAX 3                     // k16 chunks: k=7:2, k=9:2, k=11:3

__constant__ int c_dils[NDIL] = {1, 2, 4, 8, 16};

// ---------------------------------------------------------------------------
// Device-global scratch
// ---------------------------------------------------------------------------
__device__ uint8_t g_kidx[N_KERNELS];
__device__ uint8_t g_didx[N_KERNELS];
__device__ uint8_t g_garr[N_KERNELS];
__device__ int     g_sorted[N_KERNELS];
__device__ int     g_nch;
__device__ int4    g_chunks[MAXCH];          // {start, count, k, didx}
__device__ int     g_rng_bad;
__device__ __align__(16) uint4 g_wfrag[MAXCH * 2 * NKMAX * 32]; // A fragments
__device__ float   g_biasT[MAXCH * CHUNK];
__device__ __align__(16) uint g_xpair[BATCH * NDIL * XPAIR];    // {xh[i],xh[i+d]}

// ---------------------------------------------------------------------------
// NumPy default_rng(0): SeedSequence -> PCG64 (XSL-RR) -> Lemire  (validated)
// ---------------------------------------------------------------------------
#define PCG_MH 2549297995355413924ull
#define PCG_ML 4865540595714422341ull

struct Pcg { ull shi, slo, ihi, ilo; int has32; uint buf; };

__device__ __forceinline__ void mul128(ull alo, ull ahi, ull blo, ull bhi,
                                       ull &rlo, ull &rhi) {
    rlo = alo * blo;
    rhi = __umul64hi(alo, blo) + alo * bhi + ahi * blo;
}
__device__ __forceinline__ void add128(ull &alo, ull &ahi, ull blo, ull bhi) {
    ull t = alo + blo;
    ahi = ahi + bhi + (t < alo ? 1ull : 0ull);
    alo = t;
}
__device__ __forceinline__ void pcg_step(Pcg &p) {
    ull nlo, nhi;
    mul128(p.slo, p.shi, PCG_ML, PCG_MH, nlo, nhi);
    add128(nlo, nhi, p.ilo, p.ihi);
    p.slo = nlo; p.shi = nhi;
}
__device__ __forceinline__ ull pcg_out(ull slo, ull shi) {
    uint rot = (uint)(shi >> 58);
    ull x = shi ^ slo;
    return (x >> rot) | (x << ((64u - rot) & 63u));
}
__device__ __forceinline__ uint pcg_next32(Pcg &p) {
    if (p.has32) { p.has32 = 0; return p.buf; }
    pcg_step(p);
    ull v = pcg_out(p.slo, p.shi);
    p.has32 = 1;
    p.buf = (uint)(v >> 32);
    return (uint)v;
}
__device__ __forceinline__ uint lemire32(Pcg &p, uint excl) {
    ull m = (ull)pcg_next32(p) * (ull)excl;
    uint leftover = (uint)m;
    if (leftover < excl) {
        uint thr = (uint)(0u - excl) % excl;
        while (leftover < thr) {
            m = (ull)pcg_next32(p) * (ull)excl;
            leftover = (uint)m;
        }
    }
    return (uint)(m >> 32);
}
__device__ __forceinline__ uint hashmix32(uint v, uint *hc) {
    v ^= *hc; *hc *= 0x931e8875u; v *= *hc; v ^= v >> 16; return v;
}
__device__ __forceinline__ uint mix32(uint x, uint y) {
    uint r = x * 0xca01f9ddu - y * 0x4973f715u;
    r ^= r >> 16; return r;
}
__device__ void pcg_seed0(Pcg &p) {
    uint pool[4];
    uint hc = 0x43b0d7e5u;
    for (int i = 0; i < 4; i++) pool[i] = hashmix32(0u, &hc);
    for (int s = 0; s < 4; s++)
        for (int d = 0; d < 4; d++)
            if (s != d) pool[d] = mix32(pool[d], hashmix32(pool[s], &hc));
    uint hb = 0x8b51f9ddu;
    uint w32[8];
    for (int i = 0; i < 8; i++) {
        uint v = pool[i & 3];
        v ^= hb; hb *= 0x58f38dedu; v *= hb; v ^= v >> 16;
        w32[i] = v;
    }
    ull s0 = (ull)w32[0] | ((ull)w32[1] << 32);
    ull s1 = (ull)w32[2] | ((ull)w32[3] << 32);
    ull s2 = (ull)w32[4] | ((ull)w32[5] << 32);
    ull s3 = (ull)w32[6] | ((ull)w32[7] << 32);
    p.shi = 0; p.slo = 0;
    p.ihi = (s2 << 1) | (s3 >> 63);
    p.ilo = (s3 << 1) | 1ull;
    p.has32 = 0; p.buf = 0;
    pcg_step(p);
    add128(p.slo, p.shi, s1, s0);
    pcg_step(p);
}

__global__ void rng_reset() { g_rng_bad = 0; }

__global__ void rng_par() {
    int n = blockIdx.x * blockDim.x + threadIdx.x;
    if (n >= N_KERNELS) return;
    Pcg p;
    pcg_seed0(p);
    ull delta = (ull)(n + 1);
    ull am_lo = 1, am_hi = 0, ap_lo = 0, ap_hi = 0;
    ull cm_lo = PCG_ML, cm_hi = PCG_MH;
    ull cp_lo = p.ilo, cp_hi = p.ihi;
    while (delta) {
        if (delta & 1) {
            ull tlo, thi;
            mul128(am_lo, am_hi, cm_lo, cm_hi, tlo, thi);
            am_lo = tlo; am_hi = thi;
            mul128(ap_lo, ap_hi, cm_lo, cm_hi, tlo, thi);
            add128(tlo, thi, cp_lo, cp_hi);
            ap_lo = tlo; ap_hi = thi;
        }
        ull e_lo = cm_lo + 1;
        ull e_hi = cm_hi + (e_lo == 0 ? 1ull : 0ull);
        ull tlo, thi;
        mul128(e_lo, e_hi, cp_lo, cp_hi, tlo, thi);
        cp_lo = tlo; cp_hi = thi;
        mul128(cm_lo, cm_hi, cm_lo, cm_hi, tlo, thi);
        cm_lo = tlo; cm_hi = thi;
        delta >>= 1;
    }
    ull slo, shi;
    mul128(p.slo, p.shi, am_lo, am_hi, slo, shi);
    add128(slo, shi, ap_lo, ap_hi);
    ull out = pcg_out(slo, shi);
    uint lo = (uint)out;
    uint hi = (uint)(out >> 32);
    if (lo == 0u || hi == 0u) atomicOr(&g_rng_bad, 1);
    if (n < N_KERNELS / 2) {
        int j = 2 * n;
        g_kidx[j]     = (uint8_t)(((ull)lo * 3ull) >> 32);
        g_kidx[j + 1] = (uint8_t)(((ull)hi * 3ull) >> 32);
    } else {
        int j = 2 * n - N_KERNELS;
        g_didx[j]     = (uint8_t)(((ull)lo * 5ull) >> 32);
        g_didx[j + 1] = (uint8_t)(((ull)hi * 5ull) >> 32);
    }
}

__global__ void rng_seq() {
    if (threadIdx.x != 0 || blockIdx.x != 0) return;
    if (g_rng_bad == 0) return;
    Pcg p;
    pcg_seed0(p);
    for (int i = 0; i < N_KERNELS; i++) g_kidx[i] = (uint8_t)lemire32(p, 3u);
    for (int i = 0; i < N_KERNELS; i++) g_didx[i] = (uint8_t)lemire32(p, 5u);
}

// ---------------------------------------------------------------------------
// Fused grouping: single block, smem histogram -> offsets/chunks -> scatter
// ---------------------------------------------------------------------------
__global__ void __launch_bounds__(1024)
group_fused() {
    __shared__ int cnt[NGROUPS];
    __shared__ int off[NGROUPS];
    int tid = threadIdx.x;
    if (tid < NGROUPS) cnt[tid] = 0;
    __syncthreads();

    for (int i = tid; i < N_KERNELS; i += 1024) {
        int g = (int)g_kidx[i] * 5 + (int)g_didx[i];
        g_garr[i] = (uint8_t)g;
        atomicAdd(&cnt[g], 1);
    }
    __syncthreads();

    if (tid == 0) {
        int o = 0, nch = 0;
        for (int g = 0; g < NGROUPS; g++) {
            int ks   = 7 + 2 * (g / 5);
            int didx = g % 5;
            int n    = cnt[g];
            off[g] = o;
            for (int s = 0; s < n; s += CHUNK) {
                int4 ch;
                ch.x = o + s;
                ch.y = (n - s < CHUNK) ? (n - s) : CHUNK;
                ch.z = ks;
                ch.w = didx;
                g_chunks[nch++] = ch;
            }
            o += n;
        }
        g_nch = nch;
    }
    __syncthreads();

    for (int i = tid; i < N_KERNELS; i += 1024) {
        int p = atomicAdd(&off[g_garr[i]], 1);
        g_sorted[p] = i;
    }
}

// ---------------------------------------------------------------------------
// A-fragment image: fp16 weights, tap-pair K layout.
// Per channel c: S = k+1 slots (even); slot j<k holds w[c][j], slot k = 0.
// Global K slot kk = c*S + j for kk < 3S, zero beyond. mma fragment order:
//   x={(r0,2t),(r0,2t+1)}, y={(r0+8,..)}, z={(r0,2t+8),(r0,2t+9)}, w={(r0+8,..)}
// ---------------------------------------------------------------------------
__device__ __forceinline__ unsigned short whalf(const float* __restrict__ weights,
                                                const int* __restrict__ sorted,
                                                int start, int count, int k,
                                                int row, int slot) {
    int S = k + 1;
    float v = 0.0f;
    if (row < count && slot < 3 * S) {
        int c = slot / S;
        int j = slot - c * S;
        if (j < k)
            v = weights[sorted[start + row] * W_STRIDE + c * MAXK + j];
    }
    __half h = __float2half(v);
    unsigned short u;
    memcpy(&u, &h, 2);
    return u;
}

__global__ void wimg_kernel(const float* __restrict__ weights,
                            const float* __restrict__ biases) {
    int ci = blockIdx.x;
    if (ci >= g_nch) return;
    int4 ch = g_chunks[ci];
    int start = ch.x, count = ch.y, k = ch.z;

    for (int idx = threadIdx.x; idx < 2 * NKMAX * 32; idx += blockDim.x) {
        int mt   = idx / (NKMAX * 32);
        int rem  = idx - mt * (NKMAX * 32);
        int kc   = rem / 32;
        int lane = rem & 31;
        int g = lane >> 2;
        int t = lane & 3;
        int r0 = mt * 16 + g;
        int r1 = r0 + 8;
        int k0 = kc * 16 + 2 * t;
        uint4 f;
        f.x = (uint)whalf(weights, g_sorted, start, count, k, r0, k0)
            | ((uint)whalf(weights, g_sorted, start, count, k, r0, k0 + 1) << 16);
        f.y = (uint)whalf(weights, g_sorted, start, count, k, r1, k0)
            | ((uint)whalf(weights, g_sorted, start, count, k, r1, k0 + 1) << 16);
        f.z = (uint)whalf(weights, g_sorted, start, count, k, r0, k0 + 8)
            | ((uint)whalf(weights, g_sorted, start, count, k, r0, k0 + 9) << 16);
        f.w = (uint)whalf(weights, g_sorted, start, count, k, r1, k0 + 8)
            | ((uint)whalf(weights, g_sorted, start, count, k, r1, k0 + 9) << 16);
        g_wfrag[(ci * 2 + mt) * (NKMAX * 32) + kc * 32 + lane] = f;
    }
    if (threadIdx.x < CHUNK) {
        float b = 0.0f;
        if (threadIdx.x < count) b = biases[g_sorted[start + threadIdx.x]];
        g_biasT[ci * CHUNK + threadIdx.x] = b;
    }
}

// ---------------------------------------------------------------------------
// Pair image per (batch, dilation): P[c][i] = {fp16(x[i-PADL]), fp16(x[i-PADL+d])}
// (zeros outside [0, T_LEN)). Independent of the RNG.
// ---------------------------------------------------------------------------
__global__ void xpair_kernel(const float* __restrict__ x) {
    int d_idx = blockIdx.x;
    int b = blockIdx.y;
    int dil = c_dils[d_idx];
    uint* dst = g_xpair + (b * NDIL + d_idx) * XPAIR;
    const float* xb = x + b * IN_CH * T_LEN;
    for (int i = threadIdx.x; i < XPAIR; i += blockDim.x) {
        int c = i / XPE;
        int p = i - c * XPE;
        int t1 = p - PADL;
        int t2 = t1 + dil;
        float f1 = ((unsigned)t1 < T_LEN) ? xb[c * T_LEN + t1] : 0.0f;
        float f2 = ((unsigned)t2 < T_LEN) ? xb[c * T_LEN + t2] : 0.0f;
        __half h1 = __float2half(f1);
        __half h2 = __float2half(f2);
        unsigned short u1, u2;
        memcpy(&u1, &h1, 2);
        memcpy(&u2, &h2, 2);
        dst[i] = (uint)u1 | ((uint)u2 << 16);
    }
}

// ---------------------------------------------------------------------------
// Main HMMA kernel
// ---------------------------------------------------------------------------
__device__ __forceinline__ void mma16816h(float c[4], uint4 a, uint b0, uint b1) {
    asm("mma.sync.aligned.m16n8k16.row.col.f32.f16.f16.f32 "
        "{%0,%1,%2,%3}, {%4,%5,%6,%7}, {%8,%9}, {%0,%1,%2,%3};"
        : "+f"(c[0]), "+f"(c[1]), "+f"(c[2]), "+f"(c[3])
        : "r"(a.x), "r"(a.y), "r"(a.z), "r"(a.w), "r"(b0), "r"(b1));
}

// Base u32 index into the pair image for EVEN K slot s (pair base tap).
// s >= 3S is kc padding (weights zero): any valid address, use 0.
template <int K>
__device__ __forceinline__ int pslot(int s, int dil) {
    const int S = K + 1;
    const int h = (K - 1) / 2;
    if (s >= 3 * S) return 0;
    int c = s / S;          // compile-time S -> mul-shift
    int j = s - c * S;      // even, <= K-1 (valid tap)
    return c * XPE + PADL + (j - h) * dil;
}

template <int K, int NK>
__device__ __forceinline__ void run_mma(int4 ch, int b, int ci,
                                        const uint* __restrict__ xs,
                                        float (*sredm)[CHUNK], int (*sredc)[CHUNK],
                                        float* __restrict__ out) {
    const int tid  = threadIdx.x;
    const int warp = tid >> 5;
    const int lane = tid & 31;
    const int g = lane >> 2;
    const int t = lane & 3;
    const int dil = 1 << ch.w;
    const int wg = warp * 256 + g;

    // B base indices (u32) per kc for this lane
    uint ix0[NK], ix1[NK];
    #pragma unroll
    for (int kc = 0; kc < NK; kc++) {
        ix0[kc] = (uint)(pslot<K>(kc * 16 + 2 * t, dil) + wg);
        ix1[kc] = (uint)(pslot<K>(kc * 16 + 2 * t + 8, dil) + wg);
    }

    // A fragments (registers for the whole block)
    uint4 a0[NK], a1[NK];
    {
        const uint4* wf = g_wfrag + (ci * 2) * (NKMAX * 32);
        #pragma unroll
        for (int kc = 0; kc < NK; kc++) {
            a0[kc] = wf[kc * 32 + lane];
            a1[kc] = wf[NKMAX * 32 + kc * 32 + lane];
        }
    }

    // negated biases for this thread's 4 C rows
    float nb[4];
    nb[0] = -g_biasT[ci * CHUNK + g];
    nb[1] = -g_biasT[ci * CHUNK + g + 8];
    nb[2] = -g_biasT[ci * CHUNK + 16 + g];
    nb[3] = -g_biasT[ci * CHUNK + 24 + g];

    float mx[4] = {-3.4e38f, -3.4e38f, -3.4e38f, -3.4e38f};
    int ct[4] = {0, 0, 0, 0};

    #pragma unroll 8
    for (int nt = 0; nt < 32; nt++) {
        float C0[4] = {0, 0, 0, 0};
        float C1[4] = {0, 0, 0, 0};
        #pragma unroll
        for (int kc = 0; kc < NK; kc++) {
            uint b0 = xs[ix0[kc] + nt * 8];
            uint b1 = xs[ix1[kc] + nt * 8];
            mma16816h(C0, a0[kc], b0, b1);
            mma16816h(C1, a1[kc], b0, b1);
        }
        mx[0] = fmaxf(mx[0], fmaxf(C0[0], C0[1]));
        mx[1] = fmaxf(mx[1], fmaxf(C0[2], C0[3]));
        mx[2] = fmaxf(mx[2], fmaxf(C1[0], C1[1]));
        mx[3] = fmaxf(mx[3], fmaxf(C1[2], C1[3]));
        if (C0[0] > nb[0]) ct[0]++;
        if (C0[1] > nb[0]) ct[0]++;
        if (C0[2] > nb[1]) ct[1]++;
        if (C0[3] > nb[1]) ct[1]++;
        if (C1[0] > nb[2]) ct[2]++;
        if (C1[1] > nb[2]) ct[2]++;
        if (C1[2] > nb[3]) ct[3]++;
        if (C1[3] > nb[3]) ct[3]++;
    }

    // reduce across the 4 threads sharing each row
    #pragma unroll
    for (int o = 1; o <= 2; o <<= 1) {
        #pragma unroll
        for (int i = 0; i < 4; i++) {
            mx[i] = fmaxf(mx[i], __shfl_xor_sync(0xffffffffu, mx[i], o));
            ct[i] += __shfl_xor_sync(0xffffffffu, ct[i], o);
        }
    }
    if (t == 0) {
        sredm[warp][g]      = mx[0];  sredc[warp][g]      = ct[0];
        sredm[warp][g + 8]  = mx[1];  sredc[warp][g + 8]  = ct[1];
        sredm[warp][g + 16] = mx[2];  sredc[warp][g + 16] = ct[2];
        sredm[warp][g + 24] = mx[3];  sredc[warp][g + 24] = ct[3];
    }
    __syncthreads();

    if (tid < CHUNK && tid < ch.y) {
        float m = sredm[0][tid];
        int c2 = sredc[0][tid];
        #pragma unroll
        for (int w = 1; w < 4; w++) {
            m = fmaxf(m, sredm[w][tid]);
            c2 += sredc[w][tid];
        }
        int orig = g_sorted[ch.x + tid];
        float bias = g_biasT[ci * CHUNK + tid];
        float2 o;
        o.x = m + bias;
        o.y = (float)c2 * (1.0f / 1024.0f);
        *(float2*)(out + (size_t)b * OUT_STRIDE + 2 * orig) = o;
    }
}

__global__ void __launch_bounds__(128)
rocket_mma(float* __restrict__ out) {
    int ci = blockIdx.x;
    if (ci >= g_nch) return;
    int4 ch = g_chunks[ci];
    int b = blockIdx.y;

    __shared__ __align__(16) uint xs[XPAIR];
    __shared__ float sredm[4][CHUNK];
    __shared__ int   sredc[4][CHUNK];

    // copy this (batch, dilation) pair image (912 uint4)
    {
        const uint4* src = (const uint4*)(g_xpair + (b * NDIL + ch.w) * XPAIR);
        uint4* dst = (uint4*)xs;
        #pragma unroll
        for (int i = 0; i < 8; i++) {
            int p = threadIdx.x + 128 * i;
            if (p < XPAIR / 4) dst[p] = src[p];
        }
    }
    __syncthreads();

    if (ch.z == 7)      run_mma<7, 2>(ch, b, ci, xs, sredm, sredc, out);
    else if (ch.z == 9) run_mma<9, 2>(ch, b, ci, xs, sredm, sredc, out);
    else                run_mma<11, 3>(ch, b, ci, xs, sredm, sredc, out);
}

// ---------------------------------------------------------------------------
// Launch
// ---------------------------------------------------------------------------
extern "C" void kernel_launch(void* const* d_in, const int* in_sizes, int n_in,
                              void* d_out, int out_size) {
    const float* x       = (const float*)d_in[0];
    const float* weights = (const float*)d_in[1];
    const float* biases  = (const float*)d_in[2];
    float* out = (float*)d_out;

    xpair_kernel<<<dim3(NDIL, BATCH), 128>>>(x);   // RNG-independent
    rng_reset<<<1, 1>>>();
    rng_par<<<(N_KERNELS + 255) / 256, 256>>>();
    rng_seq<<<1, 1>>>();
    group_fused<<<1, 1024>>>();
    wimg_kernel<<<MAXCH, 128>>>(weights, biases);

    rocket_mma<<<dim3(MAXCH, BATCH), 128>>>(out);
}